// round 12
// baseline (speedup 1.0000x reference)
#include <cuda_runtime.h>
#include <cuda_bf16.h>
#include <cstdint>
#include <cstddef>

#define BSZ   4
#define CDIM  128
#define CQD   16
#define NPOS  4096
#define OUT_OFF (BSZ*CDIM*NPOS)   /* 2097152 floats; attention follows */

// ----------------- device scratch (no allocation allowed) -------------------
__device__ float          g_q[BSZ*NPOS*CQD];                 // [b][n][d]
__device__ float          g_khi[BSZ*NPOS*CQD];               // [b][n][d] tf32(k)
__device__ float          g_klo[BSZ*NPOS*CQD];               // [b][n][d] k - tf32(k)
__device__ __nv_bfloat16  g_v[(size_t)BSZ*CDIM*NPOS];        // [b][c][n] bf16
__device__ float          g_Spart[BSZ*4*NPOS];               // [b][g][n] partial rowsums
__device__ float          g_Vpart[(size_t)BSZ*4*CDIM*NPOS];  // [b][g][c][n] partial PV

// ----------------- helpers ---------------------------------------------------
__device__ __forceinline__ unsigned f2tf(float f) {
    unsigned r;
    asm("cvt.rna.tf32.f32 %0, %1;" : "=r"(r) : "f"(f));
    return r;
}

__device__ __forceinline__ void mma_tf32(float c[4],
                                         unsigned a0, unsigned a1, unsigned a2, unsigned a3,
                                         unsigned b0, unsigned b1) {
    asm volatile(
        "mma.sync.aligned.m16n8k8.row.col.f32.tf32.tf32.f32 "
        "{%0,%1,%2,%3},{%4,%5,%6,%7},{%8,%9},{%0,%1,%2,%3};"
        : "+f"(c[0]), "+f"(c[1]), "+f"(c[2]), "+f"(c[3])
        : "r"(a0), "r"(a1), "r"(a2), "r"(a3), "r"(b0), "r"(b1));
}

__device__ __forceinline__ void mma_bf16(float c[4],
                                         unsigned a0, unsigned a1, unsigned a2, unsigned a3,
                                         unsigned b0, unsigned b1) {
    asm volatile(
        "mma.sync.aligned.m16n8k16.row.col.f32.bf16.bf16.f32 "
        "{%0,%1,%2,%3},{%4,%5,%6,%7},{%8,%9},{%0,%1,%2,%3};"
        : "+f"(c[0]), "+f"(c[1]), "+f"(c[2]), "+f"(c[3])
        : "r"(a0), "r"(a1), "r"(a2), "r"(a3), "r"(b0), "r"(b1));
}

__device__ __forceinline__ void ldsm_x4(unsigned& r0, unsigned& r1,
                                        unsigned& r2, unsigned& r3, unsigned addr) {
    asm volatile("ldmatrix.sync.aligned.m8n8.x4.shared.b16 {%0,%1,%2,%3}, [%4];"
                 : "=r"(r0), "=r"(r1), "=r"(r2), "=r"(r3) : "r"(addr));
}

#define CP_ASYNC16(dst, src) \
    asm volatile("cp.async.ca.shared.global [%0], [%1], 16;" \
                 :: "r"(dst), "l"(src) : "memory")
#define CP_COMMIT()  asm volatile("cp.async.commit_group;" ::: "memory")
#define CP_WAIT1()   asm volatile("cp.async.wait_group 1;" ::: "memory")
#define CP_WAIT0()   asm volatile("cp.async.wait_group 0;" ::: "memory")

// decode work item -> (r, g), items ordered by r DESCENDING for load balance
__device__ __forceinline__ void decode_item(int item, int& r, int& g) {
    r = 63; g = item;
    while (true) {
        int ng = (r >> 4) + 1;
        if (g < ng) break;
        g -= ng; r--;
    }
}

// load q A-fragments (hi/lo tf32) from a stride-20 smem tile
__device__ __forceinline__ void load_q_frags(const float* qsm, int iw, int lr, int lk,
                                             unsigned qh[2][4], unsigned ql[2][4]) {
#pragma unroll
    for (int s = 0; s < 2; s++) {
        float f0 = qsm[(iw + lr    ) * 20 + s*8 + lk    ];
        float f1 = qsm[(iw + lr + 8) * 20 + s*8 + lk    ];
        float f2 = qsm[(iw + lr    ) * 20 + s*8 + lk + 4];
        float f3 = qsm[(iw + lr + 8) * 20 + s*8 + lk + 4];
        qh[s][0] = f2tf(f0); ql[s][0] = f2tf(f0 - __uint_as_float(qh[s][0]));
        qh[s][1] = f2tf(f1); ql[s][1] = f2tf(f1 - __uint_as_float(qh[s][1]));
        qh[s][2] = f2tf(f2); ql[s][2] = f2tf(f2 - __uint_as_float(qh[s][2]));
        qh[s][3] = f2tf(f3); ql[s][3] = f2tf(f3 - __uint_as_float(qh[s][3]));
    }
}

// hi-only variant (rowsum)
__device__ __forceinline__ void load_q_frags_hi(const float* qsm, int iw, int lr, int lk,
                                                unsigned qh[2][4]) {
#pragma unroll
    for (int s = 0; s < 2; s++) {
        qh[s][0] = f2tf(qsm[(iw + lr    ) * 20 + s*8 + lk    ]);
        qh[s][1] = f2tf(qsm[(iw + lr + 8) * 20 + s*8 + lk    ]);
        qh[s][2] = f2tf(qsm[(iw + lr    ) * 20 + s*8 + lk + 4]);
        qh[s][3] = f2tf(qsm[(iw + lr + 8) * 20 + s*8 + lk + 4]);
    }
}

// ======================= K1: q,k projection (fp32; k split hi/lo) ============
__global__ void __launch_bounds__(256) qk_proj(
    const float* __restrict__ x,
    const float* __restrict__ wq, const float* __restrict__ bq,
    const float* __restrict__ wk, const float* __restrict__ bk)
{
    __shared__ float wqs[CQD*CDIM], wks[CQD*CDIM];
    int tid = threadIdx.x;
    for (int i = tid; i < CQD*CDIM; i += 256) { wqs[i] = wq[i]; wks[i] = wk[i]; }
    __syncthreads();

    int t = blockIdx.x * 256 + tid;          // 0 .. B*N-1
    int b = t >> 12;
    int n = t & (NPOS - 1);
    const float* xb = x + (size_t)b*CDIM*NPOS + n;

    float qa[CQD], ka[CQD];
#pragma unroll
    for (int d = 0; d < CQD; d++) { qa[d] = bq[d]; ka[d] = bk[d]; }

    for (int c = 0; c < CDIM; c++) {
        float xv = xb[(size_t)c * NPOS];
#pragma unroll
        for (int d = 0; d < CQD; d++) {
            qa[d] = fmaf(wqs[d*CDIM + c], xv, qa[d]);
            ka[d] = fmaf(wks[d*CDIM + c], xv, ka[d]);
        }
    }
    float* qo  = g_q   + (size_t)t * CQD;
    float* kho = g_khi + (size_t)t * CQD;
    float* klo = g_klo + (size_t)t * CQD;
#pragma unroll
    for (int d = 0; d < CQD; d++) {
        qo[d] = qa[d];
        float kh = __uint_as_float(f2tf(ka[d]));
        kho[d] = kh;
        klo[d] = ka[d] - kh;
    }
}

// ======================= K2: v projection (bf16 MMA + ldmatrix) ==============
#define VPROJ_SMEM (128*136*2 + 64*136*2)

__global__ void __launch_bounds__(256) v_proj(
    const float* __restrict__ x,
    const float* __restrict__ wv, const float* __restrict__ bv)
{
    extern __shared__ char vsmem_raw[];
    __nv_bfloat16* wsm  = (__nv_bfloat16*)vsmem_raw;
    __nv_bfloat16* xsmT = wsm + 128*136;

    int b  = blockIdx.x >> 6;
    int n0 = (blockIdx.x & 63) << 6;
    int tid  = threadIdx.x;
    int w    = tid >> 5;
    int lane = tid & 31;
    int gq   = lane >> 2;
    int tig  = lane & 3;
    int cb   = w << 4;

    const float* xb = x + (size_t)b*CDIM*NPOS;

    // stage wv -> wsm (bf16)
#pragma unroll
    for (int it = 0; it < 16; it++) {
        int idx = it * 256 + tid;           // 0..4095
        int c  = idx >> 5;
        int kq = idx & 31;
        float4 wf = *(const float4*)(wv + c*CDIM + kq*4);
        *(__nv_bfloat162*)(wsm + c*136 + kq*4)     = __float22bfloat162_rn(make_float2(wf.x, wf.y));
        *(__nv_bfloat162*)(wsm + c*136 + kq*4 + 2) = __float22bfloat162_rn(make_float2(wf.z, wf.w));
    }
    // stage x^T -> xsmT (bf16, transposed)
#pragma unroll
    for (int it = 0; it < 8; it++) {
        int idx = it * 256 + tid;           // 0..2047
        int k  = idx >> 4;
        int nq = idx & 15;
        float4 xf = *(const float4*)(xb + (size_t)k*NPOS + n0 + nq*4);
        xsmT[(nq*4    )*136 + k] = __float2bfloat16_rn(xf.x);
        xsmT[(nq*4 + 1)*136 + k] = __float2bfloat16_rn(xf.y);
        xsmT[(nq*4 + 2)*136 + k] = __float2bfloat16_rn(xf.z);
        xsmT[(nq*4 + 3)*136 + k] = __float2bfloat16_rn(xf.w);
    }
    __syncthreads();

    float acc[8][4];
    {
        float blo = bv[cb + gq], bhi = bv[cb + gq + 8];
#pragma unroll
        for (int nt = 0; nt < 8; nt++) {
            acc[nt][0] = blo; acc[nt][1] = blo;
            acc[nt][2] = bhi; acc[nt][3] = bhi;
        }
    }

    unsigned wsm_sh  = (unsigned)__cvta_generic_to_shared(wsm);
    unsigned xsm_sh  = (unsigned)__cvta_generic_to_shared(xsmT);
    unsigned a_base  = wsm_sh + ((cb + (lane & 15)) * 136 + ((lane >> 4) << 3)) * 2;
    unsigned b_row   = (lane & 7) + ((lane >> 4) << 3);
    unsigned b_base  = xsm_sh + (b_row * 136 + (((lane >> 3) & 1) << 3)) * 2;

#pragma unroll
    for (int ks8 = 0; ks8 < 8; ks8++) {
        unsigned a0, a1, a2, a3;
        ldsm_x4(a0, a1, a2, a3, a_base + (ks8 * 16) * 2);
#pragma unroll
        for (int np = 0; np < 4; np++) {
            unsigned b0, b1, b2, b3;
            ldsm_x4(b0, b1, b2, b3, b_base + ((np * 16) * 136 + ks8 * 16) * 2);
            mma_bf16(acc[np*2    ], a0, a1, a2, a3, b0, b1);
            mma_bf16(acc[np*2 + 1], a0, a1, a2, a3, b2, b3);
        }
    }

    __nv_bfloat16* vb = g_v + (size_t)b*CDIM*NPOS;
#pragma unroll
    for (int nt = 0; nt < 8; nt++) {
        int n = n0 + nt*8 + tig*2;
        *(__nv_bfloat162*)&vb[(size_t)(cb+gq  )*NPOS + n] =
            __float22bfloat162_rn(make_float2(acc[nt][0], acc[nt][1]));
        *(__nv_bfloat162*)&vb[(size_t)(cb+gq+8)*NPOS + n] =
            __float22bfloat162_rn(make_float2(acc[nt][2], acc[nt][3]));
    }
}

// ======================= K3: rowsum (2 MMAs, 3-deep cp.async, 1 sync/tile) ===
#define KT_F   (64*20)
#define KT_B   (KT_F*4)

__global__ void __launch_bounds__(256, 3) rowsum_k()
{
    __shared__ float qsm[64*20];
    __shared__ float khs[3*KT_F];
    __shared__ float kls[3*KT_F];
    __shared__ float red[64][2];

    int b = blockIdx.x & 3;
    int item = blockIdx.x >> 2;
    int r, g; decode_item(item, r, g);

    int tid = threadIdx.x;
    int i0 = r << 6;
    int col0 = g << 10;
    int colEnd = min((r + 1) << 6, col0 + 1024);
    int nt = (colEnd - col0) >> 6;

    unsigned kh_sh = (unsigned)__cvta_generic_to_shared(khs);
    unsigned kl_sh = (unsigned)__cvta_generic_to_shared(kls);
    unsigned kdst  = (tid >> 2) * 80 + (tid & 3) * 16;
    size_t   kbase = ((size_t)(b << 12) + (tid >> 2)) * CQD + (tid & 3) * 4;
    const float* khsrc = g_khi + kbase;
    const float* klsrc = g_klo + kbase;

    // stage q tile
    {
        const float4 qv = ((const float4*)(g_q +
            ((size_t)(b << 12) + i0 + (tid >> 2)) * CQD))[tid & 3];
        *(float4*)&qsm[(tid >> 2) * 20 + (tid & 3) * 4] = qv;
    }
    // prologue: tiles 0 (+1)
    CP_ASYNC16(kh_sh + kdst, khsrc + (size_t)col0 * CQD);
    CP_ASYNC16(kl_sh + kdst, klsrc + (size_t)col0 * CQD);
    CP_COMMIT();
    if (nt > 1) {
        CP_ASYNC16(kh_sh + KT_B + kdst, khsrc + (size_t)(col0 + 64) * CQD);
        CP_ASYNC16(kl_sh + KT_B + kdst, klsrc + (size_t)(col0 + 64) * CQD);
        CP_COMMIT();
    }
    __syncthreads();

    int w = tid >> 5, lane = tid & 31;
    int wr = w & 3, wc = w >> 2;
    int iw = wr << 4;
    int lr = lane >> 2, lk = lane & 3;

    unsigned qh[2][4];
    load_q_frags_hi(qsm, iw, lr, lk, qh);

    float rs0 = 0.f, rs1 = 0.f;
    int slot = 0;

    for (int t = 0; t < nt; t++) {
        if (t + 1 < nt) CP_WAIT1(); else CP_WAIT0();
        __syncthreads();                        // tile t visible; compute(t-1) done
        if (t + 2 < nt) {
            int s2 = slot + 2; if (s2 >= 3) s2 -= 3;
            CP_ASYNC16(kh_sh + s2*KT_B + kdst, khsrc + (size_t)(col0 + (t+2)*64) * CQD);
            CP_ASYNC16(kl_sh + s2*KT_B + kdst, klsrc + (size_t)(col0 + (t+2)*64) * CQD);
            CP_COMMIT();
        }
        const float* khb = khs + slot*KT_F;
        const float* klb = kls + slot*KT_F;

#pragma unroll
        for (int ntile = 0; ntile < 4; ntile++) {
            int j0 = (wc << 5) + (ntile << 3);
            float acc4[4] = {0.f, 0.f, 0.f, 0.f};
#pragma unroll
            for (int s = 0; s < 2; s++) {
                unsigned bh0 = __float_as_uint(khb[(j0 + lr) * 20 + s*8 + lk    ]);
                unsigned bh1 = __float_as_uint(khb[(j0 + lr) * 20 + s*8 + lk + 4]);
                unsigned bl0 = __float_as_uint(klb[(j0 + lr) * 20 + s*8 + lk    ]);
                unsigned bl1 = __float_as_uint(klb[(j0 + lr) * 20 + s*8 + lk + 4]);
                mma_tf32(acc4, qh[s][0], qh[s][1], qh[s][2], qh[s][3], bh0, bh1);
                mma_tf32(acc4, qh[s][0], qh[s][1], qh[s][2], qh[s][3], bl0, bl1);
            }
            rs0 += __expf(acc4[0]) + __expf(acc4[1]);
            rs1 += __expf(acc4[2]) + __expf(acc4[3]);
        }
        if (++slot == 3) slot = 0;
    }

    rs0 += __shfl_xor_sync(0xffffffffu, rs0, 1);
    rs0 += __shfl_xor_sync(0xffffffffu, rs0, 2);
    rs1 += __shfl_xor_sync(0xffffffffu, rs1, 1);
    rs1 += __shfl_xor_sync(0xffffffffu, rs1, 2);
    if (lk == 0) {
        red[iw + lr    ][wc] = rs0;
        red[iw + lr + 8][wc] = rs1;
    }
    __syncthreads();
    if (tid < 64)
        g_Spart[(((size_t)b*4 + g) << 12) + i0 + tid] = red[tid][0] + red[tid][1];
}

// ======================= K5: main pass =======================================
// 3-deep cp.async pipeline, 2 syncs/tile; e via 3 tf32 MMAs fed directly from
// pre-split hi/lo K; attention written from fragments; PV via bf16 MMA.
//   qsm 5120 | khs 3*5120 | kls 3*5120 | vsm 3*18432 | pbm 9216 | sinv 256
#define VT_B (128*72*2)
#define ATTN_SMEM (5120 + 3*KT_B + 3*KT_B + 3*VT_B + 9216 + 256)

__global__ void __launch_bounds__(256, 2) attn_main(float* __restrict__ out)
{
    extern __shared__ char smem_raw[];
    float*          qsm  = (float*)smem_raw;
    float*          khs  = qsm + 64*20;
    float*          kls  = khs + 3*KT_F;
    __nv_bfloat16*  vsm  = (__nv_bfloat16*)(kls + 3*KT_F);
    __nv_bfloat16*  pbm  = vsm + 3*128*72;
    float*          sinv = (float*)(pbm + 64*72);

    int b = blockIdx.x & 3;
    int item = blockIdx.x >> 2;
    int r, g; decode_item(item, r, g);

    int tid = threadIdx.x;
    int i0 = r << 6;
    int col0 = g << 10;
    int colEnd = min((r + 1) << 6, col0 + 1024);
    int nt = (colEnd - col0) >> 6;
    int ngg = (r >> 4) + 1;

    float* attnb = out + OUT_OFF + ((size_t)b << 24);
    const __nv_bfloat16* vbat = g_v + (size_t)b*CDIM*NPOS;

    unsigned kh_sh = (unsigned)__cvta_generic_to_shared(khs);
    unsigned kl_sh = (unsigned)__cvta_generic_to_shared(kls);
    unsigned vs_sh = (unsigned)__cvta_generic_to_shared(vsm);
    unsigned kdst  = (tid >> 2) * 80 + (tid & 3) * 16;
    size_t   kbase = ((size_t)(b << 12) + (tid >> 2)) * CQD + (tid & 3) * 4;
    const float* khsrc = g_khi + kbase;
    const float* klsrc = g_klo + kbase;

    auto stage_tile = [&](int jc, int slot) {
        CP_ASYNC16(kh_sh + slot*KT_B + kdst, khsrc + (size_t)jc * CQD);
        CP_ASYNC16(kl_sh + slot*KT_B + kdst, klsrc + (size_t)jc * CQD);
#pragma unroll
        for (int it = 0; it < 4; it++) {
            int idx = it * 256 + tid;
            int c = idx >> 3, ch = idx & 7;
            CP_ASYNC16(vs_sh + slot*VT_B + c*144 + ch*16,
                       vbat + (size_t)c*NPOS + jc + ch*8);
        }
        CP_COMMIT();
    };

    if (tid < 64) {
        float s = 0.f;
        for (int gg = 0; gg < ngg; gg++)
            s += g_Spart[(((size_t)b*4 + gg) << 12) + i0 + tid];
        sinv[tid] = 1.0f / s;
    }
    // stage q tile
    {
        const float4 qv = ((const float4*)(g_q +
            ((size_t)(b << 12) + i0 + (tid >> 2)) * CQD))[tid & 3];
        *(float4*)&qsm[(tid >> 2) * 20 + (tid & 3) * 4] = qv;
    }
    // prologue: tiles 0 (+1)
    stage_tile(col0, 0);
    if (nt > 1) stage_tile(col0 + 64, 1);
    __syncthreads();

    int w = tid >> 5, lane = tid & 31;
    int wr = w & 3, wc = w >> 2;
    int iw = wr << 4;                 // e-phase warp i-base
    int lr = lane >> 2, lk = lane & 3;
    int cb = w << 4;                  // PV-phase warp c-base

    float inv0 = sinv[iw + lr], inv1 = sinv[iw + lr + 8];

    unsigned qh[2][4], ql[2][4];
    load_q_frags(qsm, iw, lr, lk, qh, ql);

    unsigned pbm_sh = (unsigned)__cvta_generic_to_shared(pbm);
    unsigned a_base = vs_sh + ((cb + (lane & 15)) * 72 + ((lane >> 4) << 3)) * 2;
    unsigned b_row  = (lane & 7) + ((lane >> 4) << 3);
    unsigned b_base = pbm_sh + (b_row * 72 + (((lane >> 3) & 1) << 3)) * 2;

    float acc[8][4];
#pragma unroll
    for (int a = 0; a < 8; a++)
#pragma unroll
        for (int c = 0; c < 4; c++) acc[a][c] = 0.f;

    int slot = 0;
    for (int t = 0; t < nt; t++) {
        int jcol0 = col0 + t * 64;
        if (t + 1 < nt) CP_WAIT1(); else CP_WAIT0();
        __syncthreads();   // (B) tile t visible; all warps past PV(t-1)
        if (t + 2 < nt) {
            int s2 = slot + 2; if (s2 >= 3) s2 -= 3;
            stage_tile(jcol0 + 128, s2);
        }

        const float* khb = khs + slot*KT_F;
        const float* klb = kls + slot*KT_F;

        // ---- e via 3 tf32 MMAs; write attn + pbm straight from fragments ----
        float* arow0 = attnb + (size_t)(i0 + iw + lr) * NPOS + jcol0;
        float* arow1 = arow0 + (size_t)8 * NPOS;
#pragma unroll
        for (int ntile = 0; ntile < 4; ntile++) {
            int j0 = (wc << 5) + (ntile << 3);
            float acc4[4] = {0.f, 0.f, 0.f, 0.f};
#pragma unroll
            for (int s = 0; s < 2; s++) {
                unsigned bh0 = __float_as_uint(khb[(j0 + lr) * 20 + s*8 + lk    ]);
                unsigned bh1 = __float_as_uint(khb[(j0 + lr) * 20 + s*8 + lk + 4]);
                unsigned bl0 = __float_as_uint(klb[(j0 + lr) * 20 + s*8 + lk    ]);
                unsigned bl1 = __float_as_uint(klb[(j0 + lr) * 20 + s*8 + lk + 4]);
                mma_tf32(acc4, qh[s][0], qh[s][1], qh[s][2], qh[s][3], bh0, bh1);
                mma_tf32(acc4, qh[s][0], qh[s][1], qh[s][2], qh[s][3], bl0, bl1);
                mma_tf32(acc4, ql[s][0], ql[s][1], ql[s][2], ql[s][3], bh0, bh1);
            }
            float p0 = __expf(acc4[0]) * inv0;
            float p1 = __expf(acc4[1]) * inv0;
            float p2 = __expf(acc4[2]) * inv1;
            float p3 = __expf(acc4[3]) * inv1;
            int jloc = j0 + (lk << 1);
            *(float2*)(arow0 + jloc) = make_float2(p0, p1);
            *(float2*)(arow1 + jloc) = make_float2(p2, p3);
            *(__nv_bfloat162*)(pbm + (iw + lr    ) * 72 + jloc) =
                __float22bfloat162_rn(make_float2(p0, p1));
            *(__nv_bfloat162*)(pbm + (iw + lr + 8) * 72 + jloc) =
                __float22bfloat162_rn(make_float2(p2, p3));
        }
        __syncthreads();   // (C) pbm ready

        // ---- PV accumulate: bf16 m16n8k16, operands via ldmatrix ----
        unsigned a_buf = a_base + slot*VT_B;
#pragma unroll
        for (int ks4 = 0; ks4 < 4; ks4++) {
            unsigned a0, a1, a2, a3;
            ldsm_x4(a0, a1, a2, a3, a_buf + (ks4 * 16) * 2);
#pragma unroll
            for (int np = 0; np < 4; np++) {
                unsigned b0, b1, b2, b3;
                ldsm_x4(b0, b1, b2, b3,
                        b_base + ((np * 16) * 72 + ks4 * 16) * 2);
                mma_bf16(acc[np*2    ], a0, a1, a2, a3, b0, b1);
                mma_bf16(acc[np*2 + 1], a0, a1, a2, a3, b2, b3);
            }
        }
        if (++slot == 3) slot = 0;
    }

    // store partial PV: g_Vpart[b][g][c][i0+i]
    {
        int gq = lane >> 2;
        int tig = lane & 3;
        float* vp = g_Vpart + (((size_t)b*4 + g) * CDIM) * NPOS;
#pragma unroll
        for (int ntile = 0; ntile < 8; ntile++) {
            int irow = i0 + ntile*8 + tig*2;
            *(float2*)&vp[(size_t)(cb+gq  )*NPOS + irow] = make_float2(acc[ntile][0], acc[ntile][1]);
            *(float2*)&vp[(size_t)(cb+gq+8)*NPOS + irow] = make_float2(acc[ntile][2], acc[ntile][3]);
        }
    }

    // ---- fused mask-zero epilogue: rows n ≡ item (mod 160) of this batch ----
    {
        float4 z = make_float4(0.f, 0.f, 0.f, 0.f);
        for (int n = item; n < NPOS; n += 160) {
            int L = ((n >> 6) + 1) << 6;
            if (L >= NPOS) continue;
            float4* dst = (float4*)(attnb + (size_t)n * NPOS + L);
            int cnt4 = (NPOS - L) >> 2;
            for (int t4 = tid; t4 < cnt4; t4 += 256) dst[t4] = z;
        }
    }
}

// ======================= K7: finalize ========================================
__global__ void __launch_bounds__(256) finalize(
    const float* __restrict__ x, const float* __restrict__ gamma,
    float* __restrict__ out)
{
    int t = blockIdx.x * 256 + threadIdx.x;    // < B*C*N
    int n  = t & (NPOS - 1);
    int bc = t >> 12;
    int b  = bc >> 7;
    int c  = bc & 127;
    int ngg = (n >> 10) + 1;

    const float* vp = g_Vpart + ((size_t)(b*4) * CDIM + c) * NPOS + n;
    float s = 0.f;
    for (int gg = 0; gg < ngg; gg++)
        s += vp[(size_t)gg * CDIM * NPOS];
    out[t] = gamma[0] * s + x[t];
}

// ======================= launch ==============================================
extern "C" void kernel_launch(void* const* d_in, const int* in_sizes, int n_in,
                              void* d_out, int out_size)
{
    const float* x     = (const float*)d_in[0];
    const float* wq    = (const float*)d_in[1];
    const float* bq    = (const float*)d_in[2];
    const float* wk    = (const float*)d_in[3];
    const float* bk    = (const float*)d_in[4];
    const float* wv    = (const float*)d_in[5];
    const float* bv    = (const float*)d_in[6];
    const float* gamma = (const float*)d_in[7];
    float* out = (float*)d_out;

    cudaFuncSetAttribute(attn_main,
                         cudaFuncAttributeMaxDynamicSharedMemorySize, ATTN_SMEM);
    cudaFuncSetAttribute(v_proj,
                         cudaFuncAttributeMaxDynamicSharedMemorySize, VPROJ_SMEM);

    qk_proj<<<BSZ*NPOS/256, 256>>>(x, wq, bq, wk, bk);
    v_proj<<<BSZ*(NPOS/64), 256, VPROJ_SMEM>>>(x, wv, bv);
    rowsum_k<<<BSZ*160, 256>>>();
    attn_main<<<BSZ*160, 256, ATTN_SMEM>>>(out);
    finalize<<<(BSZ*CDIM*NPOS)/256, 256>>>(x, gamma, out);
}

// round 13
// speedup vs baseline: 1.0689x; 1.0689x over previous
#include <cuda_runtime.h>
#include <cuda_bf16.h>
#include <cstdint>
#include <cstddef>

#define BSZ   4
#define CDIM  128
#define CQD   16
#define NPOS  4096
#define OUT_OFF (BSZ*CDIM*NPOS)   /* 2097152 floats; attention follows */

// ----------------- device scratch (no allocation allowed) -------------------
__device__ float          g_q[BSZ*NPOS*CQD];                 // [b][n][d]
__device__ float          g_k[BSZ*NPOS*CQD];                 // [b][n][d]
__device__ __nv_bfloat16  g_v[(size_t)BSZ*CDIM*NPOS];        // [b][c][n] bf16
__device__ float          g_Spart[BSZ*4*NPOS];               // [b][g][n] partial rowsums
__device__ float          g_Vpart[(size_t)BSZ*4*CDIM*NPOS];  // [b][g][c][n] partial PV

// ----------------- helpers ---------------------------------------------------
__device__ __forceinline__ unsigned f2tf(float f) {
    unsigned r;
    asm("cvt.rna.tf32.f32 %0, %1;" : "=r"(r) : "f"(f));
    return r;
}

__device__ __forceinline__ unsigned pack_bf16x2(float a, float b) {
    __nv_bfloat162 h = __float22bfloat162_rn(make_float2(a, b));
    return *(unsigned*)&h;
}

__device__ __forceinline__ void mma_tf32(float c[4],
                                         unsigned a0, unsigned a1, unsigned a2, unsigned a3,
                                         unsigned b0, unsigned b1) {
    asm volatile(
        "mma.sync.aligned.m16n8k8.row.col.f32.tf32.tf32.f32 "
        "{%0,%1,%2,%3},{%4,%5,%6,%7},{%8,%9},{%0,%1,%2,%3};"
        : "+f"(c[0]), "+f"(c[1]), "+f"(c[2]), "+f"(c[3])
        : "r"(a0), "r"(a1), "r"(a2), "r"(a3), "r"(b0), "r"(b1));
}

__device__ __forceinline__ void mma_bf16(float c[4],
                                         unsigned a0, unsigned a1, unsigned a2, unsigned a3,
                                         unsigned b0, unsigned b1) {
    asm volatile(
        "mma.sync.aligned.m16n8k16.row.col.f32.bf16.bf16.f32 "
        "{%0,%1,%2,%3},{%4,%5,%6,%7},{%8,%9},{%0,%1,%2,%3};"
        : "+f"(c[0]), "+f"(c[1]), "+f"(c[2]), "+f"(c[3])
        : "r"(a0), "r"(a1), "r"(a2), "r"(a3), "r"(b0), "r"(b1));
}

__device__ __forceinline__ void ldsm_x4(unsigned& r0, unsigned& r1,
                                        unsigned& r2, unsigned& r3, unsigned addr) {
    asm volatile("ldmatrix.sync.aligned.m8n8.x4.shared.b16 {%0,%1,%2,%3}, [%4];"
                 : "=r"(r0), "=r"(r1), "=r"(r2), "=r"(r3) : "r"(addr));
}

#define CP_ASYNC16(dst, src) \
    asm volatile("cp.async.ca.shared.global [%0], [%1], 16;" \
                 :: "r"(dst), "l"(src) : "memory")
#define CP_COMMIT()  asm volatile("cp.async.commit_group;" ::: "memory")
#define CP_WAIT1()   asm volatile("cp.async.wait_group 1;" ::: "memory")
#define CP_WAIT0()   asm volatile("cp.async.wait_group 0;" ::: "memory")

// decode work item -> (r, g), items ordered by r DESCENDING for load balance
__device__ __forceinline__ void decode_item(int item, int& r, int& g) {
    r = 63; g = item;
    while (true) {
        int ng = (r >> 4) + 1;
        if (g < ng) break;
        g -= ng; r--;
    }
}

// load q A-fragments (hi/lo tf32) from a stride-20 smem tile
__device__ __forceinline__ void load_q_frags(const float* qsm, int iw, int lr, int lk,
                                             unsigned qh[2][4], unsigned ql[2][4]) {
#pragma unroll
    for (int s = 0; s < 2; s++) {
        float f0 = qsm[(iw + lr    ) * 20 + s*8 + lk    ];
        float f1 = qsm[(iw + lr + 8) * 20 + s*8 + lk    ];
        float f2 = qsm[(iw + lr    ) * 20 + s*8 + lk + 4];
        float f3 = qsm[(iw + lr + 8) * 20 + s*8 + lk + 4];
        qh[s][0] = f2tf(f0); ql[s][0] = f2tf(f0 - __uint_as_float(qh[s][0]));
        qh[s][1] = f2tf(f1); ql[s][1] = f2tf(f1 - __uint_as_float(qh[s][1]));
        qh[s][2] = f2tf(f2); ql[s][2] = f2tf(f2 - __uint_as_float(qh[s][2]));
        qh[s][3] = f2tf(f3); ql[s][3] = f2tf(f3 - __uint_as_float(qh[s][3]));
    }
}

// hi-only variant (rowsum)
__device__ __forceinline__ void load_q_frags_hi(const float* qsm, int iw, int lr, int lk,
                                                unsigned qh[2][4]) {
#pragma unroll
    for (int s = 0; s < 2; s++) {
        qh[s][0] = f2tf(qsm[(iw + lr    ) * 20 + s*8 + lk    ]);
        qh[s][1] = f2tf(qsm[(iw + lr + 8) * 20 + s*8 + lk    ]);
        qh[s][2] = f2tf(qsm[(iw + lr    ) * 20 + s*8 + lk + 4]);
        qh[s][3] = f2tf(qsm[(iw + lr + 8) * 20 + s*8 + lk + 4]);
    }
}

// ======================= K1: q,k projection (fp32) ===========================
__global__ void __launch_bounds__(256) qk_proj(
    const float* __restrict__ x,
    const float* __restrict__ wq, const float* __restrict__ bq,
    const float* __restrict__ wk, const float* __restrict__ bk)
{
    __shared__ float wqs[CQD*CDIM], wks[CQD*CDIM];
    int tid = threadIdx.x;
    for (int i = tid; i < CQD*CDIM; i += 256) { wqs[i] = wq[i]; wks[i] = wk[i]; }
    __syncthreads();

    int t = blockIdx.x * 256 + tid;          // 0 .. B*N-1
    int b = t >> 12;
    int n = t & (NPOS - 1);
    const float* xb = x + (size_t)b*CDIM*NPOS + n;

    float qa[CQD], ka[CQD];
#pragma unroll
    for (int d = 0; d < CQD; d++) { qa[d] = bq[d]; ka[d] = bk[d]; }

    for (int c = 0; c < CDIM; c++) {
        float xv = xb[(size_t)c * NPOS];
#pragma unroll
        for (int d = 0; d < CQD; d++) {
            qa[d] = fmaf(wqs[d*CDIM + c], xv, qa[d]);
            ka[d] = fmaf(wks[d*CDIM + c], xv, ka[d]);
        }
    }
    float* qo = g_q + (size_t)t * CQD;
    float* ko = g_k + (size_t)t * CQD;
#pragma unroll
    for (int d = 0; d < CQD; d++) { qo[d] = qa[d]; ko[d] = ka[d]; }
}

// ======================= K2: v projection (bf16 MMA + ldmatrix) ==============
#define VPROJ_SMEM (128*136*2 + 64*136*2)

__global__ void __launch_bounds__(256) v_proj(
    const float* __restrict__ x,
    const float* __restrict__ wv, const float* __restrict__ bv)
{
    extern __shared__ char vsmem_raw[];
    __nv_bfloat16* wsm  = (__nv_bfloat16*)vsmem_raw;
    __nv_bfloat16* xsmT = wsm + 128*136;

    int b  = blockIdx.x >> 6;
    int n0 = (blockIdx.x & 63) << 6;
    int tid  = threadIdx.x;
    int w    = tid >> 5;
    int lane = tid & 31;
    int gq   = lane >> 2;
    int tig  = lane & 3;
    int cb   = w << 4;

    const float* xb = x + (size_t)b*CDIM*NPOS;

    // stage wv -> wsm (bf16)
#pragma unroll
    for (int it = 0; it < 16; it++) {
        int idx = it * 256 + tid;           // 0..4095
        int c  = idx >> 5;
        int kq = idx & 31;
        float4 wf = *(const float4*)(wv + c*CDIM + kq*4);
        *(__nv_bfloat162*)(wsm + c*136 + kq*4)     = __float22bfloat162_rn(make_float2(wf.x, wf.y));
        *(__nv_bfloat162*)(wsm + c*136 + kq*4 + 2) = __float22bfloat162_rn(make_float2(wf.z, wf.w));
    }
    // stage x^T -> xsmT (bf16, transposed)
#pragma unroll
    for (int it = 0; it < 8; it++) {
        int idx = it * 256 + tid;           // 0..2047
        int k  = idx >> 4;
        int nq = idx & 15;
        float4 xf = *(const float4*)(xb + (size_t)k*NPOS + n0 + nq*4);
        xsmT[(nq*4    )*136 + k] = __float2bfloat16_rn(xf.x);
        xsmT[(nq*4 + 1)*136 + k] = __float2bfloat16_rn(xf.y);
        xsmT[(nq*4 + 2)*136 + k] = __float2bfloat16_rn(xf.z);
        xsmT[(nq*4 + 3)*136 + k] = __float2bfloat16_rn(xf.w);
    }
    __syncthreads();

    float acc[8][4];
    {
        float blo = bv[cb + gq], bhi = bv[cb + gq + 8];
#pragma unroll
        for (int nt = 0; nt < 8; nt++) {
            acc[nt][0] = blo; acc[nt][1] = blo;
            acc[nt][2] = bhi; acc[nt][3] = bhi;
        }
    }

    unsigned wsm_sh  = (unsigned)__cvta_generic_to_shared(wsm);
    unsigned xsm_sh  = (unsigned)__cvta_generic_to_shared(xsmT);
    unsigned a_base  = wsm_sh + ((cb + (lane & 15)) * 136 + ((lane >> 4) << 3)) * 2;
    unsigned b_row   = (lane & 7) + ((lane >> 4) << 3);
    unsigned b_base  = xsm_sh + (b_row * 136 + (((lane >> 3) & 1) << 3)) * 2;

#pragma unroll
    for (int ks8 = 0; ks8 < 8; ks8++) {
        unsigned a0, a1, a2, a3;
        ldsm_x4(a0, a1, a2, a3, a_base + (ks8 * 16) * 2);
#pragma unroll
        for (int np = 0; np < 4; np++) {
            unsigned b0, b1, b2, b3;
            ldsm_x4(b0, b1, b2, b3, b_base + ((np * 16) * 136 + ks8 * 16) * 2);
            mma_bf16(acc[np*2    ], a0, a1, a2, a3, b0, b1);
            mma_bf16(acc[np*2 + 1], a0, a1, a2, a3, b2, b3);
        }
    }

    __nv_bfloat16* vb = g_v + (size_t)b*CDIM*NPOS;
#pragma unroll
    for (int nt = 0; nt < 8; nt++) {
        int n = n0 + nt*8 + tig*2;
        *(__nv_bfloat162*)&vb[(size_t)(cb+gq  )*NPOS + n] =
            __float22bfloat162_rn(make_float2(acc[nt][0], acc[nt][1]));
        *(__nv_bfloat162*)&vb[(size_t)(cb+gq+8)*NPOS + n] =
            __float22bfloat162_rn(make_float2(acc[nt][2], acc[nt][3]));
    }
}

// ======================= K3: rowsum (2 MMAs, 3-deep cp.async, 1 sync/tile) ===
#define KT_F   (64*20)
#define KT_B   (KT_F*4)

__global__ void __launch_bounds__(256, 3) rowsum_k()
{
    __shared__ float qsm[64*20];
    __shared__ float ks3[3*KT_F];
    __shared__ float red[64][2];

    int b = blockIdx.x & 3;
    int item = blockIdx.x >> 2;
    int r, g; decode_item(item, r, g);

    int tid = threadIdx.x;
    int i0 = r << 6;
    int col0 = g << 10;
    int colEnd = min((r + 1) << 6, col0 + 1024);
    int nt = (colEnd - col0) >> 6;

    unsigned ks_sh = (unsigned)__cvta_generic_to_shared(ks3);
    unsigned kdst  = (tid >> 2) * 80 + (tid & 3) * 16;
    const float* ksrc = g_k + ((size_t)(b << 12) + (tid >> 2)) * CQD + (tid & 3) * 4;

    // stage q tile
    {
        const float4 qv = ((const float4*)(g_q +
            ((size_t)(b << 12) + i0 + (tid >> 2)) * CQD))[tid & 3];
        *(float4*)&qsm[(tid >> 2) * 20 + (tid & 3) * 4] = qv;
    }
    // prologue: tiles 0 (+1)
    CP_ASYNC16(ks_sh + kdst, ksrc + (size_t)col0 * CQD);
    CP_COMMIT();
    if (nt > 1) {
        CP_ASYNC16(ks_sh + KT_B + kdst, ksrc + (size_t)(col0 + 64) * CQD);
        CP_COMMIT();
    }
    __syncthreads();

    int w = tid >> 5, lane = tid & 31;
    int wr = w & 3, wc = w >> 2;
    int iw = wr << 4;
    int lr = lane >> 2, lk = lane & 3;

    unsigned qh[2][4];
    load_q_frags_hi(qsm, iw, lr, lk, qh);

    float rs0 = 0.f, rs1 = 0.f;
    int slot = 0;

    for (int t = 0; t < nt; t++) {
        if (t + 1 < nt) CP_WAIT1(); else CP_WAIT0();
        __syncthreads();                        // tile t visible; compute(t-1) done
        if (t + 2 < nt) {
            int s2 = slot + 2; if (s2 >= 3) s2 -= 3;
            CP_ASYNC16(ks_sh + s2*KT_B + kdst, ksrc + (size_t)(col0 + (t+2)*64) * CQD);
            CP_COMMIT();
        }
        const float* ksb = ks3 + slot*KT_F;

#pragma unroll
        for (int ntile = 0; ntile < 4; ntile++) {
            int j0 = (wc << 5) + (ntile << 3);
            float acc4[4] = {0.f, 0.f, 0.f, 0.f};
#pragma unroll
            for (int s = 0; s < 2; s++) {
                float f0 = ksb[(j0 + lr) * 20 + s*8 + lk    ];
                float f1 = ksb[(j0 + lr) * 20 + s*8 + lk + 4];
                unsigned bh0 = f2tf(f0), bh1 = f2tf(f1);
                unsigned bl0 = f2tf(f0 - __uint_as_float(bh0));
                unsigned bl1 = f2tf(f1 - __uint_as_float(bh1));
                mma_tf32(acc4, qh[s][0], qh[s][1], qh[s][2], qh[s][3], bh0, bh1);
                mma_tf32(acc4, qh[s][0], qh[s][1], qh[s][2], qh[s][3], bl0, bl1);
            }
            rs0 += __expf(acc4[0]) + __expf(acc4[1]);
            rs1 += __expf(acc4[2]) + __expf(acc4[3]);
        }
        if (++slot == 3) slot = 0;
    }

    rs0 += __shfl_xor_sync(0xffffffffu, rs0, 1);
    rs0 += __shfl_xor_sync(0xffffffffu, rs0, 2);
    rs1 += __shfl_xor_sync(0xffffffffu, rs1, 1);
    rs1 += __shfl_xor_sync(0xffffffffu, rs1, 2);
    if (lk == 0) {
        red[iw + lr    ][wc] = rs0;
        red[iw + lr + 8][wc] = rs1;
    }
    __syncthreads();
    if (tid < 64)
        g_Spart[(((size_t)b*4 + g) << 12) + i0 + tid] = red[tid][0] + red[tid][1];
}

// ======================= K5: main pass =======================================
// FA2-style: p stays in registers as the PV A operand (e-MMA C-frag layout ==
// bf16 A-frag layout). Warps split j (wc halves) and hold 16i x 128c partial
// accumulators, reduced cross-warp once per block. No pbm, 1 sync per tile.
//   qsm 5120 | ks 3*5120 | vsm 3*18432 | sinv 256  = 76032 B
#define VT_B (128*72*2)
#define ATTN_SMEM (5120 + 3*KT_B + 3*VT_B + 256)

__global__ void __launch_bounds__(256, 2) attn_main(float* __restrict__ out)
{
    extern __shared__ char smem_raw[];
    float*          qsm  = (float*)smem_raw;
    float*          ks3  = qsm + 64*20;
    __nv_bfloat16*  vsm  = (__nv_bfloat16*)(ks3 + 3*KT_F);
    float*          sinv = (float*)(vsm + 3*128*72);

    int b = blockIdx.x & 3;
    int item = blockIdx.x >> 2;
    int r, g; decode_item(item, r, g);

    int tid = threadIdx.x;
    int i0 = r << 6;
    int col0 = g << 10;
    int colEnd = min((r + 1) << 6, col0 + 1024);
    int nt = (colEnd - col0) >> 6;
    int ngg = (r >> 4) + 1;

    float* attnb = out + OUT_OFF + ((size_t)b << 24);
    const __nv_bfloat16* vbat = g_v + (size_t)b*CDIM*NPOS;

    unsigned ks_sh = (unsigned)__cvta_generic_to_shared(ks3);
    unsigned vs_sh = (unsigned)__cvta_generic_to_shared(vsm);
    unsigned kdst  = (tid >> 2) * 80 + (tid & 3) * 16;
    const float* ksrc = g_k + ((size_t)(b << 12) + (tid >> 2)) * CQD + (tid & 3) * 4;

    auto stage_tile = [&](int jc, int slot) {
        CP_ASYNC16(ks_sh + slot*KT_B + kdst, ksrc + (size_t)jc * CQD);
#pragma unroll
        for (int it = 0; it < 4; it++) {
            int idx = it * 256 + tid;
            int c = idx >> 3, ch = idx & 7;
            CP_ASYNC16(vs_sh + slot*VT_B + c*144 + ch*16,
                       vbat + (size_t)c*NPOS + jc + ch*8);
        }
        CP_COMMIT();
    };

    if (tid < 64) {
        float s = 0.f;
        for (int gg = 0; gg < ngg; gg++)
            s += g_Spart[(((size_t)b*4 + gg) << 12) + i0 + tid];
        sinv[tid] = 1.0f / s;
    }
    // stage q tile
    {
        const float4 qv = ((const float4*)(g_q +
            ((size_t)(b << 12) + i0 + (tid >> 2)) * CQD))[tid & 3];
        *(float4*)&qsm[(tid >> 2) * 20 + (tid & 3) * 4] = qv;
    }
    // prologue: tiles 0 (+1)
    stage_tile(col0, 0);
    if (nt > 1) stage_tile(col0 + 64, 1);
    __syncthreads();

    int w = tid >> 5, lane = tid & 31;
    int wr = w & 3, wc = w >> 2;
    int iw = wr << 4;                 // warp i-base (both phases now)
    int lr = lane >> 2, lk = lane & 3;

    float inv0 = sinv[iw + lr], inv1 = sinv[iw + lr + 8];

    unsigned qh[2][4], ql[2][4];
    load_q_frags(qsm, iw, lr, lk, qh, ql);

    // PV B-frag (V^T) ldmatrix base: rows = c, cols = j within slot
    unsigned bV0 = vs_sh + ((lane & 7) + ((lane >> 4) << 3)) * 144
                 + ((wc << 5) + (((lane >> 3) & 1) << 3)) * 2;

    float acc[16][4];
#pragma unroll
    for (int a = 0; a < 16; a++)
#pragma unroll
        for (int c = 0; c < 4; c++) acc[a][c] = 0.f;

    int slot = 0;
    for (int t = 0; t < nt; t++) {
        int jcol0 = col0 + t * 64;
        if (t + 1 < nt) CP_WAIT1(); else CP_WAIT0();
        __syncthreads();   // tile t visible; all warps past PV(t-1)
        if (t + 2 < nt) {
            int s2 = slot + 2; if (s2 >= 3) s2 -= 3;
            stage_tile(jcol0 + 128, s2);
        }

        const float* ksb = ks3 + slot*KT_F;
        unsigned pa[2][4];   // PV A-frags: [k-block][a0..a3]

        // ---- e via 3 tf32 MMAs; write attn + keep p as A-frags in regs ----
        float* arow0 = attnb + (size_t)(i0 + iw + lr) * NPOS + jcol0;
        float* arow1 = arow0 + (size_t)8 * NPOS;
#pragma unroll
        for (int ntile = 0; ntile < 4; ntile++) {
            int j0 = (wc << 5) + (ntile << 3);
            float acc4[4] = {0.f, 0.f, 0.f, 0.f};
#pragma unroll
            for (int s = 0; s < 2; s++) {
                float f0 = ksb[(j0 + lr) * 20 + s*8 + lk    ];
                float f1 = ksb[(j0 + lr) * 20 + s*8 + lk + 4];
                unsigned bh0 = f2tf(f0), bh1 = f2tf(f1);
                unsigned bl0 = f2tf(f0 - __uint_as_float(bh0));
                unsigned bl1 = f2tf(f1 - __uint_as_float(bh1));
                mma_tf32(acc4, qh[s][0], qh[s][1], qh[s][2], qh[s][3], bh0, bh1);
                mma_tf32(acc4, qh[s][0], qh[s][1], qh[s][2], qh[s][3], bl0, bl1);
                mma_tf32(acc4, ql[s][0], ql[s][1], ql[s][2], ql[s][3], bh0, bh1);
            }
            float p0 = __expf(acc4[0]) * inv0;
            float p1 = __expf(acc4[1]) * inv0;
            float p2 = __expf(acc4[2]) * inv1;
            float p3 = __expf(acc4[3]) * inv1;
            int jloc = j0 + (lk << 1);
            *(float2*)(arow0 + jloc) = make_float2(p0, p1);
            *(float2*)(arow1 + jloc) = make_float2(p2, p3);
            pa[ntile >> 1][(ntile & 1) * 2    ] = pack_bf16x2(p0, p1);
            pa[ntile >> 1][(ntile & 1) * 2 + 1] = pack_bf16x2(p2, p3);
        }

        // ---- PV: out[i][c] += p[i][j] * V^T[j][c]; A from regs, B via ldsm --
        unsigned bbase = bV0 + slot*VT_B;
#pragma unroll
        for (int kb = 0; kb < 2; kb++) {
#pragma unroll
            for (int cg = 0; cg < 8; cg++) {
                unsigned b0, b1, b2, b3;
                ldsm_x4(b0, b1, b2, b3, bbase + cg*2304 + kb*32);
                mma_bf16(acc[cg*2    ], pa[kb][0], pa[kb][1], pa[kb][2], pa[kb][3], b0, b1);
                mma_bf16(acc[cg*2 + 1], pa[kb][0], pa[kb][1], pa[kb][2], pa[kb][3], b2, b3);
            }
        }
        if (++slot == 3) slot = 0;
    }

    // ---- cross-warp reduce (wc=1 -> wc=0) and store partial PV -------------
    __syncthreads();                    // all PV reads of vsm done
    float* redbuf = (float*)vsm;        // 32KB scratch inside freed vsm
    if (wc == 1) {
        float* dst = redbuf + wr*2048 + lane;
#pragma unroll
        for (int a = 0; a < 16; a++)
#pragma unroll
            for (int c = 0; c < 4; c++)
                dst[(a*4 + c) * 32] = acc[a][c];
    }
    __syncthreads();
    if (wc == 0) {
        const float* src = redbuf + wr*2048 + lane;
        float* vp = g_Vpart + (((size_t)b*4 + g) * CDIM) * NPOS;
        int gi = lane >> 2, t2 = (lane & 3) << 1;
        int ii = i0 + iw + gi;
#pragma unroll
        for (int a = 0; a < 16; a++) {
            float v0 = acc[a][0] + src[(a*4 + 0) * 32];
            float v1 = acc[a][1] + src[(a*4 + 1) * 32];
            float v2 = acc[a][2] + src[(a*4 + 2) * 32];
            float v3 = acc[a][3] + src[(a*4 + 3) * 32];
            int cc = a*8 + t2;
            vp[(size_t)cc*NPOS + ii]         = v0;
            vp[(size_t)(cc+1)*NPOS + ii]     = v1;
            vp[(size_t)cc*NPOS + ii + 8]     = v2;
            vp[(size_t)(cc+1)*NPOS + ii + 8] = v3;
        }
    }

    // ---- fused mask-zero epilogue: rows n ≡ item (mod 160) of this batch ----
    {
        float4 z = make_float4(0.f, 0.f, 0.f, 0.f);
        for (int n = item; n < NPOS; n += 160) {
            int L = ((n >> 6) + 1) << 6;
            if (L >= NPOS) continue;
            float4* dst = (float4*)(attnb + (size_t)n * NPOS + L);
            int cnt4 = (NPOS - L) >> 2;
            for (int t4 = tid; t4 < cnt4; t4 += 256) dst[t4] = z;
        }
    }
}

// ======================= K7: finalize ========================================
__global__ void __launch_bounds__(256) finalize(
    const float* __restrict__ x, const float* __restrict__ gamma,
    float* __restrict__ out)
{
    int t = blockIdx.x * 256 + threadIdx.x;    // < B*C*N
    int n  = t & (NPOS - 1);
    int bc = t >> 12;
    int b  = bc >> 7;
    int c  = bc & 127;
    int ngg = (n >> 10) + 1;

    const float* vp = g_Vpart + ((size_t)(b*4) * CDIM + c) * NPOS + n;
    float s = 0.f;
    for (int gg = 0; gg < ngg; gg++)
        s += vp[(size_t)gg * CDIM * NPOS];
    out[t] = gamma[0] * s + x[t];
}

// ======================= launch ==============================================
extern "C" void kernel_launch(void* const* d_in, const int* in_sizes, int n_in,
                              void* d_out, int out_size)
{
    const float* x     = (const float*)d_in[0];
    const float* wq    = (const float*)d_in[1];
    const float* bq    = (const float*)d_in[2];
    const float* wk    = (const float*)d_in[3];
    const float* bk    = (const float*)d_in[4];
    const float* wv    = (const float*)d_in[5];
    const float* bv    = (const float*)d_in[6];
    const float* gamma = (const float*)d_in[7];
    float* out = (float*)d_out;

    cudaFuncSetAttribute(attn_main,
                         cudaFuncAttributeMaxDynamicSharedMemorySize, ATTN_SMEM);
    cudaFuncSetAttribute(v_proj,
                         cudaFuncAttributeMaxDynamicSharedMemorySize, VPROJ_SMEM);

    qk_proj<<<BSZ*NPOS/256, 256>>>(x, wq, bq, wk, bk);
    v_proj<<<BSZ*(NPOS/64), 256, VPROJ_SMEM>>>(x, wv, bv);
    rowsum_k<<<BSZ*160, 256>>>();
    attn_main<<<BSZ*160, 256, ATTN_SMEM>>>(out);
    finalize<<<(BSZ*CDIM*NPOS)/256, 256>>>(x, gamma, out);
}

// round 14
// speedup vs baseline: 1.3750x; 1.2864x over previous
#include <cuda_runtime.h>
#include <cuda_bf16.h>
#include <cstdint>
#include <cstddef>

#define BSZ   4
#define CDIM  128
#define CQD   16
#define NPOS  4096
#define OUT_OFF (BSZ*CDIM*NPOS)   /* 2097152 floats; attention follows */

// ----------------- device scratch (no allocation allowed) -------------------
__device__ float          g_q[BSZ*NPOS*CQD];                 // [b][n][d]
__device__ float          g_k[BSZ*NPOS*CQD];                 // [b][n][d]
__device__ __nv_bfloat16  g_v[(size_t)BSZ*CDIM*NPOS];        // [b][c][n] bf16
__device__ float          g_Spart[BSZ*4*NPOS];               // [b][g][n] partial rowsums
__device__ float          g_Vpart[(size_t)BSZ*4*CDIM*NPOS];  // [b][g][c][n] partial PV

// ----------------- helpers ---------------------------------------------------
__device__ __forceinline__ unsigned f2tf(float f) {
    unsigned r;
    asm("cvt.rna.tf32.f32 %0, %1;" : "=r"(r) : "f"(f));
    return r;
}

__device__ __forceinline__ unsigned pack_bf16x2(float a, float b) {
    __nv_bfloat162 h = __float22bfloat162_rn(make_float2(a, b));
    return *(unsigned*)&h;
}

__device__ __forceinline__ void mma_tf32(float c[4],
                                         unsigned a0, unsigned a1, unsigned a2, unsigned a3,
                                         unsigned b0, unsigned b1) {
    asm volatile(
        "mma.sync.aligned.m16n8k8.row.col.f32.tf32.tf32.f32 "
        "{%0,%1,%2,%3},{%4,%5,%6,%7},{%8,%9},{%0,%1,%2,%3};"
        : "+f"(c[0]), "+f"(c[1]), "+f"(c[2]), "+f"(c[3])
        : "r"(a0), "r"(a1), "r"(a2), "r"(a3), "r"(b0), "r"(b1));
}

__device__ __forceinline__ void mma_bf16(float c[4],
                                         unsigned a0, unsigned a1, unsigned a2, unsigned a3,
                                         unsigned b0, unsigned b1) {
    asm volatile(
        "mma.sync.aligned.m16n8k16.row.col.f32.bf16.bf16.f32 "
        "{%0,%1,%2,%3},{%4,%5,%6,%7},{%8,%9},{%0,%1,%2,%3};"
        : "+f"(c[0]), "+f"(c[1]), "+f"(c[2]), "+f"(c[3])
        : "r"(a0), "r"(a1), "r"(a2), "r"(a3), "r"(b0), "r"(b1));
}

__device__ __forceinline__ void ldsm_x4(unsigned& r0, unsigned& r1,
                                        unsigned& r2, unsigned& r3, unsigned addr) {
    asm volatile("ldmatrix.sync.aligned.m8n8.x4.shared.b16 {%0,%1,%2,%3}, [%4];"
                 : "=r"(r0), "=r"(r1), "=r"(r2), "=r"(r3) : "r"(addr));
}

#define CP_ASYNC16(dst, src) \
    asm volatile("cp.async.ca.shared.global [%0], [%1], 16;" \
                 :: "r"(dst), "l"(src) : "memory")
#define CP_COMMIT()  asm volatile("cp.async.commit_group;" ::: "memory")
#define CP_WAIT1()   asm volatile("cp.async.wait_group 1;" ::: "memory")
#define CP_WAIT0()   asm volatile("cp.async.wait_group 0;" ::: "memory")

// decode work item -> (r, g), items ordered by r DESCENDING for load balance
__device__ __forceinline__ void decode_item(int item, int& r, int& g) {
    r = 63; g = item;
    while (true) {
        int ng = (r >> 4) + 1;
        if (g < ng) break;
        g -= ng; r--;
    }
}

// load q A-fragments (hi/lo tf32) from a stride-20 smem tile
__device__ __forceinline__ void load_q_frags(const float* qsm, int iw, int lr, int lk,
                                             unsigned qh[2][4], unsigned ql[2][4]) {
#pragma unroll
    for (int s = 0; s < 2; s++) {
        float f0 = qsm[(iw + lr    ) * 20 + s*8 + lk    ];
        float f1 = qsm[(iw + lr + 8) * 20 + s*8 + lk    ];
        float f2 = qsm[(iw + lr    ) * 20 + s*8 + lk + 4];
        float f3 = qsm[(iw + lr + 8) * 20 + s*8 + lk + 4];
        qh[s][0] = f2tf(f0); ql[s][0] = f2tf(f0 - __uint_as_float(qh[s][0]));
        qh[s][1] = f2tf(f1); ql[s][1] = f2tf(f1 - __uint_as_float(qh[s][1]));
        qh[s][2] = f2tf(f2); ql[s][2] = f2tf(f2 - __uint_as_float(qh[s][2]));
        qh[s][3] = f2tf(f3); ql[s][3] = f2tf(f3 - __uint_as_float(qh[s][3]));
    }
}

// hi-only variant (rowsum)
__device__ __forceinline__ void load_q_frags_hi(const float* qsm, int iw, int lr, int lk,
                                                unsigned qh[2][4]) {
#pragma unroll
    for (int s = 0; s < 2; s++) {
        qh[s][0] = f2tf(qsm[(iw + lr    ) * 20 + s*8 + lk    ]);
        qh[s][1] = f2tf(qsm[(iw + lr + 8) * 20 + s*8 + lk    ]);
        qh[s][2] = f2tf(qsm[(iw + lr    ) * 20 + s*8 + lk + 4]);
        qh[s][3] = f2tf(qsm[(iw + lr + 8) * 20 + s*8 + lk + 4]);
    }
}

// ======================= K1: q,k projection (split-tf32 MMA) =================
// D[n][d] = sum_c x^T[n][c] * W[d][c] + bias[d], d = 0..15 -> q, 16..31 -> k.
// A = x^T (transpose-staged fp32, stride 132), B = fused (wq;wk) row-major
// [d][c] which IS col-major [c][d] — fed directly. 3-MMA split-tf32.
// smem: xT 64*132 f32 (33792B) | whi 32*132 (16896B) | wlo 32*132 (16896B)
#define QK_SMEM ((64*132 + 32*132 + 32*132) * 4)

__global__ void __launch_bounds__(256) qk_proj_mma(
    const float* __restrict__ x,
    const float* __restrict__ wq, const float* __restrict__ bq,
    const float* __restrict__ wk, const float* __restrict__ bk)
{
    extern __shared__ float qksm[];
    float* xT  = qksm;               // [64][132]
    float* whi = xT + 64*132;        // [32][132]
    float* wlo = whi + 32*132;       // [32][132]

    int b  = blockIdx.x >> 6;
    int n0 = (blockIdx.x & 63) << 6;
    int tid  = threadIdx.x;
    int lane = tid & 31;
    int w    = tid >> 5;
    int wr   = w & 3;                // n-subtile (16 rows)
    int wd   = w >> 2;               // 0 -> q half, 1 -> k half

    const float* xb = x + (size_t)b*CDIM*NPOS;

    // stage W (fused q;k) split hi/lo
#pragma unroll
    for (int it = 0; it < 16; it++) {
        int idx = it * 256 + tid;    // 0..4095
        int d = idx >> 7, c = idx & 127;
        float wv = (d < 16) ? wq[d*CDIM + c] : wk[(d-16)*CDIM + c];
        float hi = __uint_as_float(f2tf(wv));
        whi[d*132 + c] = hi;
        wlo[d*132 + c] = wv - hi;
    }
    // stage x^T (fp32 transpose: read float4 over n, scatter to rows)
#pragma unroll
    for (int it = 0; it < 8; it++) {
        int idx = it * 256 + tid;    // 0..2047
        int c   = idx >> 4;
        int nn4 = idx & 15;
        float4 xf = *(const float4*)(xb + (size_t)c*NPOS + n0 + nn4*4);
        xT[(nn4*4    )*132 + c] = xf.x;
        xT[(nn4*4 + 1)*132 + c] = xf.y;
        xT[(nn4*4 + 2)*132 + c] = xf.z;
        xT[(nn4*4 + 3)*132 + c] = xf.w;
    }
    __syncthreads();

    int lr = lane >> 2, lk = lane & 3;
    int nb = wr << 4;

    float acc[2][4];
    {
        const float* bias = wd ? bk : bq;
        float b0 = bias[2*lk], b1 = bias[2*lk + 1];
        float b2 = bias[8 + 2*lk], b3 = bias[8 + 2*lk + 1];
        acc[0][0] = b0; acc[0][1] = b1; acc[0][2] = b0; acc[0][3] = b1;
        acc[1][0] = b2; acc[1][1] = b3; acc[1][2] = b2; acc[1][3] = b3;
    }

#pragma unroll
    for (int ks = 0; ks < 16; ks++) {
        int kc = ks * 8;
        // A frags (hi/lo)
        float f0 = xT[(nb + lr    )*132 + kc + lk    ];
        float f1 = xT[(nb + lr + 8)*132 + kc + lk    ];
        float f2 = xT[(nb + lr    )*132 + kc + lk + 4];
        float f3 = xT[(nb + lr + 8)*132 + kc + lk + 4];
        unsigned ah0 = f2tf(f0), ah1 = f2tf(f1), ah2 = f2tf(f2), ah3 = f2tf(f3);
        unsigned al0 = f2tf(f0 - __uint_as_float(ah0));
        unsigned al1 = f2tf(f1 - __uint_as_float(ah1));
        unsigned al2 = f2tf(f2 - __uint_as_float(ah2));
        unsigned al3 = f2tf(f3 - __uint_as_float(ah3));
#pragma unroll
        for (int dt = 0; dt < 2; dt++) {
            int drow = (wd << 4) + (dt << 3) + lr;   // B stored as [d][c]
            unsigned bh0 = __float_as_uint(whi[drow*132 + kc + lk    ]);
            unsigned bh1 = __float_as_uint(whi[drow*132 + kc + lk + 4]);
            unsigned bl0 = __float_as_uint(wlo[drow*132 + kc + lk    ]);
            unsigned bl1 = __float_as_uint(wlo[drow*132 + kc + lk + 4]);
            mma_tf32(acc[dt], ah0, ah1, ah2, ah3, bh0, bh1);
            mma_tf32(acc[dt], ah0, ah1, ah2, ah3, bl0, bl1);
            mma_tf32(acc[dt], al0, al1, al2, al3, bh0, bh1);
        }
    }

    // write out: rows n, cols d (within q or k half)
    float* dst = wd ? g_k : g_q;
#pragma unroll
    for (int dt = 0; dt < 2; dt++) {
        int dcol = (dt << 3) + 2*lk;
        int n_r0 = n0 + nb + lr;
        *(float2*)&dst[((size_t)(b << 12) + n_r0    ) * CQD + dcol] =
            make_float2(acc[dt][0], acc[dt][1]);
        *(float2*)&dst[((size_t)(b << 12) + n_r0 + 8) * CQD + dcol] =
            make_float2(acc[dt][2], acc[dt][3]);
    }
}

// ======================= K2: v projection (bf16 MMA + ldmatrix) ==============
#define VPROJ_SMEM (128*136*2 + 64*136*2)

__global__ void __launch_bounds__(256) v_proj(
    const float* __restrict__ x,
    const float* __restrict__ wv, const float* __restrict__ bv)
{
    extern __shared__ char vsmem_raw[];
    __nv_bfloat16* wsm  = (__nv_bfloat16*)vsmem_raw;
    __nv_bfloat16* xsmT = wsm + 128*136;

    int b  = blockIdx.x >> 6;
    int n0 = (blockIdx.x & 63) << 6;
    int tid  = threadIdx.x;
    int w    = tid >> 5;
    int lane = tid & 31;
    int gq   = lane >> 2;
    int tig  = lane & 3;
    int cb   = w << 4;

    const float* xb = x + (size_t)b*CDIM*NPOS;

    // stage wv -> wsm (bf16)
#pragma unroll
    for (int it = 0; it < 16; it++) {
        int idx = it * 256 + tid;           // 0..4095
        int c  = idx >> 5;
        int kq = idx & 31;
        float4 wf = *(const float4*)(wv + c*CDIM + kq*4);
        *(__nv_bfloat162*)(wsm + c*136 + kq*4)     = __float22bfloat162_rn(make_float2(wf.x, wf.y));
        *(__nv_bfloat162*)(wsm + c*136 + kq*4 + 2) = __float22bfloat162_rn(make_float2(wf.z, wf.w));
    }
    // stage x^T -> xsmT (bf16, transposed)
#pragma unroll
    for (int it = 0; it < 8; it++) {
        int idx = it * 256 + tid;           // 0..2047
        int k  = idx >> 4;
        int nq = idx & 15;
        float4 xf = *(const float4*)(xb + (size_t)k*NPOS + n0 + nq*4);
        xsmT[(nq*4    )*136 + k] = __float2bfloat16_rn(xf.x);
        xsmT[(nq*4 + 1)*136 + k] = __float2bfloat16_rn(xf.y);
        xsmT[(nq*4 + 2)*136 + k] = __float2bfloat16_rn(xf.z);
        xsmT[(nq*4 + 3)*136 + k] = __float2bfloat16_rn(xf.w);
    }
    __syncthreads();

    float acc[8][4];
    {
        float blo = bv[cb + gq], bhi = bv[cb + gq + 8];
#pragma unroll
        for (int nt = 0; nt < 8; nt++) {
            acc[nt][0] = blo; acc[nt][1] = blo;
            acc[nt][2] = bhi; acc[nt][3] = bhi;
        }
    }

    unsigned wsm_sh  = (unsigned)__cvta_generic_to_shared(wsm);
    unsigned xsm_sh  = (unsigned)__cvta_generic_to_shared(xsmT);
    unsigned a_base  = wsm_sh + ((cb + (lane & 15)) * 136 + ((lane >> 4) << 3)) * 2;
    unsigned b_row   = (lane & 7) + ((lane >> 4) << 3);
    unsigned b_base  = xsm_sh + (b_row * 136 + (((lane >> 3) & 1) << 3)) * 2;

#pragma unroll
    for (int ks8 = 0; ks8 < 8; ks8++) {
        unsigned a0, a1, a2, a3;
        ldsm_x4(a0, a1, a2, a3, a_base + (ks8 * 16) * 2);
#pragma unroll
        for (int np = 0; np < 4; np++) {
            unsigned b0, b1, b2, b3;
            ldsm_x4(b0, b1, b2, b3, b_base + ((np * 16) * 136 + ks8 * 16) * 2);
            mma_bf16(acc[np*2    ], a0, a1, a2, a3, b0, b1);
            mma_bf16(acc[np*2 + 1], a0, a1, a2, a3, b2, b3);
        }
    }

    __nv_bfloat16* vb = g_v + (size_t)b*CDIM*NPOS;
#pragma unroll
    for (int nt = 0; nt < 8; nt++) {
        int n = n0 + nt*8 + tig*2;
        *(__nv_bfloat162*)&vb[(size_t)(cb+gq  )*NPOS + n] =
            __float22bfloat162_rn(make_float2(acc[nt][0], acc[nt][1]));
        *(__nv_bfloat162*)&vb[(size_t)(cb+gq+8)*NPOS + n] =
            __float22bfloat162_rn(make_float2(acc[nt][2], acc[nt][3]));
    }
}

// ======================= K3: rowsum (2 MMAs, 3-deep cp.async, 1 sync/tile) ===
#define KT_F   (64*20)
#define KT_B   (KT_F*4)

__global__ void __launch_bounds__(256, 3) rowsum_k()
{
    __shared__ float qsm[64*20];
    __shared__ float ks3[3*KT_F];
    __shared__ float red[64][2];

    int b = blockIdx.x & 3;
    int item = blockIdx.x >> 2;
    int r, g; decode_item(item, r, g);

    int tid = threadIdx.x;
    int i0 = r << 6;
    int col0 = g << 10;
    int colEnd = min((r + 1) << 6, col0 + 1024);
    int nt = (colEnd - col0) >> 6;

    unsigned ks_sh = (unsigned)__cvta_generic_to_shared(ks3);
    unsigned kdst  = (tid >> 2) * 80 + (tid & 3) * 16;
    const float* ksrc = g_k + ((size_t)(b << 12) + (tid >> 2)) * CQD + (tid & 3) * 4;

    // stage q tile
    {
        const float4 qv = ((const float4*)(g_q +
            ((size_t)(b << 12) + i0 + (tid >> 2)) * CQD))[tid & 3];
        *(float4*)&qsm[(tid >> 2) * 20 + (tid & 3) * 4] = qv;
    }
    // prologue: tiles 0 (+1)
    CP_ASYNC16(ks_sh + kdst, ksrc + (size_t)col0 * CQD);
    CP_COMMIT();
    if (nt > 1) {
        CP_ASYNC16(ks_sh + KT_B + kdst, ksrc + (size_t)(col0 + 64) * CQD);
        CP_COMMIT();
    }
    __syncthreads();

    int w = tid >> 5, lane = tid & 31;
    int wr = w & 3, wc = w >> 2;
    int iw = wr << 4;
    int lr = lane >> 2, lk = lane & 3;

    unsigned qh[2][4];
    load_q_frags_hi(qsm, iw, lr, lk, qh);

    float rs0 = 0.f, rs1 = 0.f;
    int slot = 0;

    for (int t = 0; t < nt; t++) {
        if (t + 1 < nt) CP_WAIT1(); else CP_WAIT0();
        __syncthreads();                        // tile t visible; compute(t-1) done
        if (t + 2 < nt) {
            int s2 = slot + 2; if (s2 >= 3) s2 -= 3;
            CP_ASYNC16(ks_sh + s2*KT_B + kdst, ksrc + (size_t)(col0 + (t+2)*64) * CQD);
            CP_COMMIT();
        }
        const float* ksb = ks3 + slot*KT_F;

#pragma unroll
        for (int ntile = 0; ntile < 4; ntile++) {
            int j0 = (wc << 5) + (ntile << 3);
            float acc4[4] = {0.f, 0.f, 0.f, 0.f};
#pragma unroll
            for (int s = 0; s < 2; s++) {
                float f0 = ksb[(j0 + lr) * 20 + s*8 + lk    ];
                float f1 = ksb[(j0 + lr) * 20 + s*8 + lk + 4];
                unsigned bh0 = f2tf(f0), bh1 = f2tf(f1);
                unsigned bl0 = f2tf(f0 - __uint_as_float(bh0));
                unsigned bl1 = f2tf(f1 - __uint_as_float(bh1));
                mma_tf32(acc4, qh[s][0], qh[s][1], qh[s][2], qh[s][3], bh0, bh1);
                mma_tf32(acc4, qh[s][0], qh[s][1], qh[s][2], qh[s][3], bl0, bl1);
            }
            rs0 += __expf(acc4[0]) + __expf(acc4[1]);
            rs1 += __expf(acc4[2]) + __expf(acc4[3]);
        }
        if (++slot == 3) slot = 0;
    }

    rs0 += __shfl_xor_sync(0xffffffffu, rs0, 1);
    rs0 += __shfl_xor_sync(0xffffffffu, rs0, 2);
    rs1 += __shfl_xor_sync(0xffffffffu, rs1, 1);
    rs1 += __shfl_xor_sync(0xffffffffu, rs1, 2);
    if (lk == 0) {
        red[iw + lr    ][wc] = rs0;
        red[iw + lr + 8][wc] = rs1;
    }
    __syncthreads();
    if (tid < 64)
        g_Spart[(((size_t)b*4 + g) << 12) + i0 + tid] = red[tid][0] + red[tid][1];
}

// ======================= K5: main pass =======================================
// FA2-style: p stays in registers as the PV A operand. Warps split j (wc
// halves), hold 16i x 128c partial accumulators, reduced cross-warp once.
//   qsm 5120 | ks 3*5120 | vsm 3*18432 | sinv 256  = 76032 B
#define VT_B (128*72*2)
#define ATTN_SMEM (5120 + 3*KT_B + 3*VT_B + 256)

__global__ void __launch_bounds__(256, 2) attn_main(float* __restrict__ out)
{
    extern __shared__ char smem_raw[];
    float*          qsm  = (float*)smem_raw;
    float*          ks3  = qsm + 64*20;
    __nv_bfloat16*  vsm  = (__nv_bfloat16*)(ks3 + 3*KT_F);
    float*          sinv = (float*)(vsm + 3*128*72);

    int b = blockIdx.x & 3;
    int item = blockIdx.x >> 2;
    int r, g; decode_item(item, r, g);

    int tid = threadIdx.x;
    int i0 = r << 6;
    int col0 = g << 10;
    int colEnd = min((r + 1) << 6, col0 + 1024);
    int nt = (colEnd - col0) >> 6;
    int ngg = (r >> 4) + 1;

    float* attnb = out + OUT_OFF + ((size_t)b << 24);
    const __nv_bfloat16* vbat = g_v + (size_t)b*CDIM*NPOS;

    unsigned ks_sh = (unsigned)__cvta_generic_to_shared(ks3);
    unsigned vs_sh = (unsigned)__cvta_generic_to_shared(vsm);
    unsigned kdst  = (tid >> 2) * 80 + (tid & 3) * 16;
    const float* ksrc = g_k + ((size_t)(b << 12) + (tid >> 2)) * CQD + (tid & 3) * 4;

    auto stage_tile = [&](int jc, int slot) {
        CP_ASYNC16(ks_sh + slot*KT_B + kdst, ksrc + (size_t)jc * CQD);
#pragma unroll
        for (int it = 0; it < 4; it++) {
            int idx = it * 256 + tid;
            int c = idx >> 3, ch = idx & 7;
            CP_ASYNC16(vs_sh + slot*VT_B + c*144 + ch*16,
                       vbat + (size_t)c*NPOS + jc + ch*8);
        }
        CP_COMMIT();
    };

    if (tid < 64) {
        float s = 0.f;
        for (int gg = 0; gg < ngg; gg++)
            s += g_Spart[(((size_t)b*4 + gg) << 12) + i0 + tid];
        sinv[tid] = 1.0f / s;
    }
    // stage q tile
    {
        const float4 qv = ((const float4*)(g_q +
            ((size_t)(b << 12) + i0 + (tid >> 2)) * CQD))[tid & 3];
        *(float4*)&qsm[(tid >> 2) * 20 + (tid & 3) * 4] = qv;
    }
    // prologue: tiles 0 (+1)
    stage_tile(col0, 0);
    if (nt > 1) stage_tile(col0 + 64, 1);
    __syncthreads();

    int w = tid >> 5, lane = tid & 31;
    int wr = w & 3, wc = w >> 2;
    int iw = wr << 4;                 // warp i-base (both phases now)
    int lr = lane >> 2, lk = lane & 3;

    float inv0 = sinv[iw + lr], inv1 = sinv[iw + lr + 8];

    unsigned qh[2][4], ql[2][4];
    load_q_frags(qsm, iw, lr, lk, qh, ql);

    // PV B-frag (V^T) ldmatrix base: rows = c, cols = j within slot
    unsigned bV0 = vs_sh + ((lane & 7) + ((lane >> 4) << 3)) * 144
                 + ((wc << 5) + (((lane >> 3) & 1) << 3)) * 2;

    float acc[16][4];
#pragma unroll
    for (int a = 0; a < 16; a++)
#pragma unroll
        for (int c = 0; c < 4; c++) acc[a][c] = 0.f;

    int slot = 0;
    for (int t = 0; t < nt; t++) {
        int jcol0 = col0 + t * 64;
        if (t + 1 < nt) CP_WAIT1(); else CP_WAIT0();
        __syncthreads();   // tile t visible; all warps past PV(t-1)
        if (t + 2 < nt) {
            int s2 = slot + 2; if (s2 >= 3) s2 -= 3;
            stage_tile(jcol0 + 128, s2);
        }

        const float* ksb = ks3 + slot*KT_F;
        unsigned pa[2][4];   // PV A-frags: [k-block][a0..a3]

        // ---- e via 3 tf32 MMAs; write attn + keep p as A-frags in regs ----
        float* arow0 = attnb + (size_t)(i0 + iw + lr) * NPOS + jcol0;
        float* arow1 = arow0 + (size_t)8 * NPOS;
#pragma unroll
        for (int ntile = 0; ntile < 4; ntile++) {
            int j0 = (wc << 5) + (ntile << 3);
            float acc4[4] = {0.f, 0.f, 0.f, 0.f};
#pragma unroll
            for (int s = 0; s < 2; s++) {
                float f0 = ksb[(j0 + lr) * 20 + s*8 + lk    ];
                float f1 = ksb[(j0 + lr) * 20 + s*8 + lk + 4];
                unsigned bh0 = f2tf(f0), bh1 = f2tf(f1);
                unsigned bl0 = f2tf(f0 - __uint_as_float(bh0));
                unsigned bl1 = f2tf(f1 - __uint_as_float(bh1));
                mma_tf32(acc4, qh[s][0], qh[s][1], qh[s][2], qh[s][3], bh0, bh1);
                mma_tf32(acc4, qh[s][0], qh[s][1], qh[s][2], qh[s][3], bl0, bl1);
                mma_tf32(acc4, ql[s][0], ql[s][1], ql[s][2], ql[s][3], bh0, bh1);
            }
            float p0 = __expf(acc4[0]) * inv0;
            float p1 = __expf(acc4[1]) * inv0;
            float p2 = __expf(acc4[2]) * inv1;
            float p3 = __expf(acc4[3]) * inv1;
            int jloc = j0 + (lk << 1);
            *(float2*)(arow0 + jloc) = make_float2(p0, p1);
            *(float2*)(arow1 + jloc) = make_float2(p2, p3);
            pa[ntile >> 1][(ntile & 1) * 2    ] = pack_bf16x2(p0, p1);
            pa[ntile >> 1][(ntile & 1) * 2 + 1] = pack_bf16x2(p2, p3);
        }

        // ---- PV: out[i][c] += p[i][j] * V^T[j][c]; A from regs, B via ldsm --
        unsigned bbase = bV0 + slot*VT_B;
#pragma unroll
        for (int kb = 0; kb < 2; kb++) {
#pragma unroll
            for (int cg = 0; cg < 8; cg++) {
                unsigned b0, b1, b2, b3;
                ldsm_x4(b0, b1, b2, b3, bbase + cg*2304 + kb*32);
                mma_bf16(acc[cg*2    ], pa[kb][0], pa[kb][1], pa[kb][2], pa[kb][3], b0, b1);
                mma_bf16(acc[cg*2 + 1], pa[kb][0], pa[kb][1], pa[kb][2], pa[kb][3], b2, b3);
            }
        }
        if (++slot == 3) slot = 0;
    }

    // ---- cross-warp reduce (wc=1 -> wc=0) and store partial PV -------------
    __syncthreads();                    // all PV reads of vsm done
    float* redbuf = (float*)vsm;        // 32KB scratch inside freed vsm
    if (wc == 1) {
        float* dst = redbuf + wr*2048 + lane;
#pragma unroll
        for (int a = 0; a < 16; a++)
#pragma unroll
            for (int c = 0; c < 4; c++)
                dst[(a*4 + c) * 32] = acc[a][c];
    }
    __syncthreads();
    if (wc == 0) {
        const float* src = redbuf + wr*2048 + lane;
        float* vp = g_Vpart + (((size_t)b*4 + g) * CDIM) * NPOS;
        int gi = lane >> 2, t2 = (lane & 3) << 1;
        int ii = i0 + iw + gi;
#pragma unroll
        for (int a = 0; a < 16; a++) {
            float v0 = acc[a][0] + src[(a*4 + 0) * 32];
            float v1 = acc[a][1] + src[(a*4 + 1) * 32];
            float v2 = acc[a][2] + src[(a*4 + 2) * 32];
            float v3 = acc[a][3] + src[(a*4 + 3) * 32];
            int cc = a*8 + t2;
            vp[(size_t)cc*NPOS + ii]         = v0;
            vp[(size_t)(cc+1)*NPOS + ii]     = v1;
            vp[(size_t)cc*NPOS + ii + 8]     = v2;
            vp[(size_t)(cc+1)*NPOS + ii + 8] = v3;
        }
    }

    // ---- fused mask-zero epilogue: rows n ≡ item (mod 160) of this batch ----
    {
        float4 z = make_float4(0.f, 0.f, 0.f, 0.f);
        for (int n = item; n < NPOS; n += 160) {
            int L = ((n >> 6) + 1) << 6;
            if (L >= NPOS) continue;
            float4* dst = (float4*)(attnb + (size_t)n * NPOS + L);
            int cnt4 = (NPOS - L) >> 2;
            for (int t4 = tid; t4 < cnt4; t4 += 256) dst[t4] = z;
        }
    }
}

// ======================= K7: finalize ========================================
__global__ void __launch_bounds__(256) finalize(
    const float* __restrict__ x, const float* __restrict__ gamma,
    float* __restrict__ out)
{
    int t = blockIdx.x * 256 + threadIdx.x;    // < B*C*N
    int n  = t & (NPOS - 1);
    int bc = t >> 12;
    int b  = bc >> 7;
    int c  = bc & 127;
    int ngg = (n >> 10) + 1;

    const float* vp = g_Vpart + ((size_t)(b*4) * CDIM + c) * NPOS + n;
    float s = 0.f;
    for (int gg = 0; gg < ngg; gg++)
        s += vp[(size_t)gg * CDIM * NPOS];
    out[t] = gamma[0] * s + x[t];
}

// ======================= launch ==============================================
extern "C" void kernel_launch(void* const* d_in, const int* in_sizes, int n_in,
                              void* d_out, int out_size)
{
    const float* x     = (const float*)d_in[0];
    const float* wq    = (const float*)d_in[1];
    const float* bq    = (const float*)d_in[2];
    const float* wk    = (const float*)d_in[3];
    const float* bk    = (const float*)d_in[4];
    const float* wv    = (const float*)d_in[5];
    const float* bv    = (const float*)d_in[6];
    const float* gamma = (const float*)d_in[7];
    float* out = (float*)d_out;

    cudaFuncSetAttribute(attn_main,
                         cudaFuncAttributeMaxDynamicSharedMemorySize, ATTN_SMEM);
    cudaFuncSetAttribute(v_proj,
                         cudaFuncAttributeMaxDynamicSharedMemorySize, VPROJ_SMEM);
    cudaFuncSetAttribute(qk_proj_mma,
                         cudaFuncAttributeMaxDynamicSharedMemorySize, QK_SMEM);

    qk_proj_mma<<<BSZ*64, 256, QK_SMEM>>>(x, wq, bq, wk, bk);
    v_proj<<<BSZ*(NPOS/64), 256, VPROJ_SMEM>>>(x, wv, bv);
    rowsum_k<<<BSZ*160, 256>>>();
    attn_main<<<BSZ*160, 256, ATTN_SMEM>>>(out);
    finalize<<<(BSZ*CDIM*NPOS)/256, 256>>>(x, gamma, out);
}

// round 16
// speedup vs baseline: 1.3968x; 1.0158x over previous
#include <cuda_runtime.h>
#include <cuda_bf16.h>
#include <cstdint>
#include <cstddef>

#define BSZ   4
#define CDIM  128
#define CQD   16
#define NPOS  4096
#define OUT_OFF (BSZ*CDIM*NPOS)   /* 2097152 floats; attention follows */
#define LOG2E 1.4426950408889634f

// ----------------- device scratch (no allocation allowed) -------------------
__device__ float          g_q[BSZ*NPOS*CQD];                 // [b][n][d]  (pre-scaled by log2e)
__device__ float          g_k[BSZ*NPOS*CQD];                 // [b][n][d]
__device__ __nv_bfloat16  g_v[(size_t)BSZ*CDIM*NPOS];        // [b][c][n] bf16
__device__ float          g_Spart[BSZ*4*NPOS];               // [b][g][n] partial rowsums
__device__ float          g_Vpart[(size_t)BSZ*4*CDIM*NPOS];  // [b][g][c][n] partial PV

// ----------------- helpers ---------------------------------------------------
__device__ __forceinline__ unsigned f2tf(float f) {
    unsigned r;
    asm("cvt.rna.tf32.f32 %0, %1;" : "=r"(r) : "f"(f));
    return r;
}

__device__ __forceinline__ float ex2f(float x) {
    float y;
    asm("ex2.approx.f32 %0, %1;" : "=f"(y) : "f"(x));
    return y;
}

__device__ __forceinline__ unsigned pack_bf16x2(float a, float b) {
    __nv_bfloat162 h = __float22bfloat162_rn(make_float2(a, b));
    return *(unsigned*)&h;
}

__device__ __forceinline__ void mma_tf32(float c[4],
                                         unsigned a0, unsigned a1, unsigned a2, unsigned a3,
                                         unsigned b0, unsigned b1) {
    asm volatile(
        "mma.sync.aligned.m16n8k8.row.col.f32.tf32.tf32.f32 "
        "{%0,%1,%2,%3},{%4,%5,%6,%7},{%8,%9},{%0,%1,%2,%3};"
        : "+f"(c[0]), "+f"(c[1]), "+f"(c[2]), "+f"(c[3])
        : "r"(a0), "r"(a1), "r"(a2), "r"(a3), "r"(b0), "r"(b1));
}

__device__ __forceinline__ void mma_bf16(float c[4],
                                         unsigned a0, unsigned a1, unsigned a2, unsigned a3,
                                         unsigned b0, unsigned b1) {
    asm volatile(
        "mma.sync.aligned.m16n8k16.row.col.f32.bf16.bf16.f32 "
        "{%0,%1,%2,%3},{%4,%5,%6,%7},{%8,%9},{%0,%1,%2,%3};"
        : "+f"(c[0]), "+f"(c[1]), "+f"(c[2]), "+f"(c[3])
        : "r"(a0), "r"(a1), "r"(a2), "r"(a3), "r"(b0), "r"(b1));
}

__device__ __forceinline__ void ldsm_x4(unsigned& r0, unsigned& r1,
                                        unsigned& r2, unsigned& r3, unsigned addr) {
    asm volatile("ldmatrix.sync.aligned.m8n8.x4.shared.b16 {%0,%1,%2,%3}, [%4];"
                 : "=r"(r0), "=r"(r1), "=r"(r2), "=r"(r3) : "r"(addr));
}

#define CP_ASYNC16(dst, src) \
    asm volatile("cp.async.ca.shared.global [%0], [%1], 16;" \
                 :: "r"(dst), "l"(src) : "memory")
#define CP_COMMIT()  asm volatile("cp.async.commit_group;" ::: "memory")
#define CP_WAIT1()   asm volatile("cp.async.wait_group 1;" ::: "memory")
#define CP_WAIT0()   asm volatile("cp.async.wait_group 0;" ::: "memory")

// decode work item -> (r, g), items ordered by r DESCENDING for load balance
__device__ __forceinline__ void decode_item(int item, int& r, int& g) {
    r = 63; g = item;
    while (true) {
        int ng = (r >> 4) + 1;
        if (g < ng) break;
        g -= ng; r--;
    }
}

// load q A-fragments (hi/lo tf32) from a stride-20 smem tile
__device__ __forceinline__ void load_q_frags(const float* qsm, int iw, int lr, int lk,
                                             unsigned qh[2][4], unsigned ql[2][4]) {
#pragma unroll
    for (int s = 0; s < 2; s++) {
        float f0 = qsm[(iw + lr    ) * 20 + s*8 + lk    ];
        float f1 = qsm[(iw + lr + 8) * 20 + s*8 + lk    ];
        float f2 = qsm[(iw + lr    ) * 20 + s*8 + lk + 4];
        float f3 = qsm[(iw + lr + 8) * 20 + s*8 + lk + 4];
        qh[s][0] = f2tf(f0); ql[s][0] = f2tf(f0 - __uint_as_float(qh[s][0]));
        qh[s][1] = f2tf(f1); ql[s][1] = f2tf(f1 - __uint_as_float(qh[s][1]));
        qh[s][2] = f2tf(f2); ql[s][2] = f2tf(f2 - __uint_as_float(qh[s][2]));
        qh[s][3] = f2tf(f3); ql[s][3] = f2tf(f3 - __uint_as_float(qh[s][3]));
    }
}

// hi-only variant (rowsum)
__device__ __forceinline__ void load_q_frags_hi(const float* qsm, int iw, int lr, int lk,
                                                unsigned qh[2][4]) {
#pragma unroll
    for (int s = 0; s < 2; s++) {
        qh[s][0] = f2tf(qsm[(iw + lr    ) * 20 + s*8 + lk    ]);
        qh[s][1] = f2tf(qsm[(iw + lr + 8) * 20 + s*8 + lk    ]);
        qh[s][2] = f2tf(qsm[(iw + lr    ) * 20 + s*8 + lk + 4]);
        qh[s][3] = f2tf(qsm[(iw + lr + 8) * 20 + s*8 + lk + 4]);
    }
}

// ======================= K1: q,k projection (split-tf32 MMA) =================
// D[n][d] = sum_c x^T[n][c] * W[d][c] + bias[d], d = 0..15 -> q, 16..31 -> k.
// q-half weights/bias pre-scaled by log2e so downstream exp becomes ex2.
#define QK_SMEM ((64*132 + 32*132 + 32*132) * 4)

__global__ void __launch_bounds__(256) qk_proj_mma(
    const float* __restrict__ x,
    const float* __restrict__ wq, const float* __restrict__ bq,
    const float* __restrict__ wk, const float* __restrict__ bk)
{
    extern __shared__ float qksm[];
    float* xT  = qksm;               // [64][132]
    float* whi = xT + 64*132;        // [32][132]
    float* wlo = whi + 32*132;       // [32][132]

    int b  = blockIdx.x >> 6;
    int n0 = (blockIdx.x & 63) << 6;
    int tid  = threadIdx.x;
    int lane = tid & 31;
    int w    = tid >> 5;
    int wr   = w & 3;                // n-subtile (16 rows)
    int wd   = w >> 2;               // 0 -> q half, 1 -> k half

    const float* xb = x + (size_t)b*CDIM*NPOS;

    // stage W (fused q;k) split hi/lo; q-half scaled by log2e
#pragma unroll
    for (int it = 0; it < 16; it++) {
        int idx = it * 256 + tid;    // 0..4095
        int d = idx >> 7, c = idx & 127;
        float wv = (d < 16) ? wq[d*CDIM + c] * LOG2E : wk[(d-16)*CDIM + c];
        float hi = __uint_as_float(f2tf(wv));
        whi[d*132 + c] = hi;
        wlo[d*132 + c] = wv - hi;
    }
    // stage x^T (fp32 transpose: read float4 over n, scatter to rows)
#pragma unroll
    for (int it = 0; it < 8; it++) {
        int idx = it * 256 + tid;    // 0..2047
        int c   = idx >> 4;
        int nn4 = idx & 15;
        float4 xf = *(const float4*)(xb + (size_t)c*NPOS + n0 + nn4*4);
        xT[(nn4*4    )*132 + c] = xf.x;
        xT[(nn4*4 + 1)*132 + c] = xf.y;
        xT[(nn4*4 + 2)*132 + c] = xf.z;
        xT[(nn4*4 + 3)*132 + c] = xf.w;
    }
    __syncthreads();

    int lr = lane >> 2, lk = lane & 3;
    int nb = wr << 4;

    float acc[2][4];
    {
        const float* bias = wd ? bk : bq;
        float scale = wd ? 1.0f : LOG2E;
        float b0 = bias[2*lk] * scale,     b1 = bias[2*lk + 1] * scale;
        float b2 = bias[8 + 2*lk] * scale, b3 = bias[8 + 2*lk + 1] * scale;
        acc[0][0] = b0; acc[0][1] = b1; acc[0][2] = b0; acc[0][3] = b1;
        acc[1][0] = b2; acc[1][1] = b3; acc[1][2] = b2; acc[1][3] = b3;
    }

#pragma unroll
    for (int ks = 0; ks < 16; ks++) {
        int kc = ks * 8;
        // A frags (hi/lo)
        float f0 = xT[(nb + lr    )*132 + kc + lk    ];
        float f1 = xT[(nb + lr + 8)*132 + kc + lk    ];
        float f2 = xT[(nb + lr    )*132 + kc + lk + 4];
        float f3 = xT[(nb + lr + 8)*132 + kc + lk + 4];
        unsigned ah0 = f2tf(f0), ah1 = f2tf(f1), ah2 = f2tf(f2), ah3 = f2tf(f3);
        unsigned al0 = f2tf(f0 - __uint_as_float(ah0));
        unsigned al1 = f2tf(f1 - __uint_as_float(ah1));
        unsigned al2 = f2tf(f2 - __uint_as_float(ah2));
        unsigned al3 = f2tf(f3 - __uint_as_float(ah3));
#pragma unroll
        for (int dt = 0; dt < 2; dt++) {
            int drow = (wd << 4) + (dt << 3) + lr;   // B stored as [d][c]
            unsigned bh0 = __float_as_uint(whi[drow*132 + kc + lk    ]);
            unsigned bh1 = __float_as_uint(whi[drow*132 + kc + lk + 4]);
            unsigned bl0 = __float_as_uint(wlo[drow*132 + kc + lk    ]);
            unsigned bl1 = __float_as_uint(wlo[drow*132 + kc + lk + 4]);
            mma_tf32(acc[dt], ah0, ah1, ah2, ah3, bh0, bh1);
            mma_tf32(acc[dt], ah0, ah1, ah2, ah3, bl0, bl1);
            mma_tf32(acc[dt], al0, al1, al2, al3, bh0, bh1);
        }
    }

    // write out: rows n, cols d (within q or k half)
    float* dst = wd ? g_k : g_q;
#pragma unroll
    for (int dt = 0; dt < 2; dt++) {
        int dcol = (dt << 3) + 2*lk;
        int n_r0 = n0 + nb + lr;
        *(float2*)&dst[((size_t)(b << 12) + n_r0    ) * CQD + dcol] =
            make_float2(acc[dt][0], acc[dt][1]);
        *(float2*)&dst[((size_t)(b << 12) + n_r0 + 8) * CQD + dcol] =
            make_float2(acc[dt][2], acc[dt][3]);
    }
}

// ======================= K2: v projection (bf16 MMA + ldmatrix) ==============
#define VPROJ_SMEM (128*136*2 + 64*136*2)

__global__ void __launch_bounds__(256) v_proj(
    const float* __restrict__ x,
    const float* __restrict__ wv, const float* __restrict__ bv)
{
    extern __shared__ char vsmem_raw[];
    __nv_bfloat16* wsm  = (__nv_bfloat16*)vsmem_raw;
    __nv_bfloat16* xsmT = wsm + 128*136;

    int b  = blockIdx.x >> 6;
    int n0 = (blockIdx.x & 63) << 6;
    int tid  = threadIdx.x;
    int w    = tid >> 5;
    int lane = tid & 31;
    int gq   = lane >> 2;
    int tig  = lane & 3;
    int cb   = w << 4;

    const float* xb = x + (size_t)b*CDIM*NPOS;

    // stage wv -> wsm (bf16)
#pragma unroll
    for (int it = 0; it < 16; it++) {
        int idx = it * 256 + tid;           // 0..4095
        int c  = idx >> 5;
        int kq = idx & 31;
        float4 wf = *(const float4*)(wv + c*CDIM + kq*4);
        *(__nv_bfloat162*)(wsm + c*136 + kq*4)     = __float22bfloat162_rn(make_float2(wf.x, wf.y));
        *(__nv_bfloat162*)(wsm + c*136 + kq*4 + 2) = __float22bfloat162_rn(make_float2(wf.z, wf.w));
    }
    // stage x^T -> xsmT (bf16, transposed)
#pragma unroll
    for (int it = 0; it < 8; it++) {
        int idx = it * 256 + tid;           // 0..2047
        int k  = idx >> 4;
        int nq = idx & 15;
        float4 xf = *(const float4*)(xb + (size_t)k*NPOS + n0 + nq*4);
        xsmT[(nq*4    )*136 + k] = __float2bfloat16_rn(xf.x);
        xsmT[(nq*4 + 1)*136 + k] = __float2bfloat16_rn(xf.y);
        xsmT[(nq*4 + 2)*136 + k] = __float2bfloat16_rn(xf.z);
        xsmT[(nq*4 + 3)*136 + k] = __float2bfloat16_rn(xf.w);
    }
    __syncthreads();

    float acc[8][4];
    {
        float blo = bv[cb + gq], bhi = bv[cb + gq + 8];
#pragma unroll
        for (int nt = 0; nt < 8; nt++) {
            acc[nt][0] = blo; acc[nt][1] = blo;
            acc[nt][2] = bhi; acc[nt][3] = bhi;
        }
    }

    unsigned wsm_sh  = (unsigned)__cvta_generic_to_shared(wsm);
    unsigned xsm_sh  = (unsigned)__cvta_generic_to_shared(xsmT);
    unsigned a_base  = wsm_sh + ((cb + (lane & 15)) * 136 + ((lane >> 4) << 3)) * 2;
    unsigned b_row   = (lane & 7) + ((lane >> 4) << 3);
    unsigned b_base  = xsm_sh + (b_row * 136 + (((lane >> 3) & 1) << 3)) * 2;

#pragma unroll
    for (int ks8 = 0; ks8 < 8; ks8++) {
        unsigned a0, a1, a2, a3;
        ldsm_x4(a0, a1, a2, a3, a_base + (ks8 * 16) * 2);
#pragma unroll
        for (int np = 0; np < 4; np++) {
            unsigned b0, b1, b2, b3;
            ldsm_x4(b0, b1, b2, b3, b_base + ((np * 16) * 136 + ks8 * 16) * 2);
            mma_bf16(acc[np*2    ], a0, a1, a2, a3, b0, b1);
            mma_bf16(acc[np*2 + 1], a0, a1, a2, a3, b2, b3);
        }
    }

    __nv_bfloat16* vb = g_v + (size_t)b*CDIM*NPOS;
#pragma unroll
    for (int nt = 0; nt < 8; nt++) {
        int n = n0 + nt*8 + tig*2;
        *(__nv_bfloat162*)&vb[(size_t)(cb+gq  )*NPOS + n] =
            __float22bfloat162_rn(make_float2(acc[nt][0], acc[nt][1]));
        *(__nv_bfloat162*)&vb[(size_t)(cb+gq+8)*NPOS + n] =
            __float22bfloat162_rn(make_float2(acc[nt][2], acc[nt][3]));
    }
}

// ======================= K3: rowsum (2 MMAs, ILP-2 pairs, cp.async) ==========
#define KT_F   (64*20)
#define KT_B   (KT_F*4)

__global__ void __launch_bounds__(256, 3) rowsum_k()
{
    __shared__ float qsm[64*20];
    __shared__ float ks3[3*KT_F];
    __shared__ float red[64][2];

    int b = blockIdx.x & 3;
    int item = blockIdx.x >> 2;
    int r, g; decode_item(item, r, g);

    int tid = threadIdx.x;
    int i0 = r << 6;
    int col0 = g << 10;
    int colEnd = min((r + 1) << 6, col0 + 1024);
    int nt = (colEnd - col0) >> 6;

    unsigned ks_sh = (unsigned)__cvta_generic_to_shared(ks3);
    unsigned kdst  = (tid >> 2) * 80 + (tid & 3) * 16;
    const float* ksrc = g_k + ((size_t)(b << 12) + (tid >> 2)) * CQD + (tid & 3) * 4;

    // stage q tile
    {
        const float4 qv = ((const float4*)(g_q +
            ((size_t)(b << 12) + i0 + (tid >> 2)) * CQD))[tid & 3];
        *(float4*)&qsm[(tid >> 2) * 20 + (tid & 3) * 4] = qv;
    }
    // prologue: tiles 0 (+1)
    CP_ASYNC16(ks_sh + kdst, ksrc + (size_t)col0 * CQD);
    CP_COMMIT();
    if (nt > 1) {
        CP_ASYNC16(ks_sh + KT_B + kdst, ksrc + (size_t)(col0 + 64) * CQD);
        CP_COMMIT();
    }
    __syncthreads();

    int w = tid >> 5, lane = tid & 31;
    int wr = w & 3, wc = w >> 2;
    int iw = wr << 4;
    int lr = lane >> 2, lk = lane & 3;

    unsigned qh[2][4];
    load_q_frags_hi(qsm, iw, lr, lk, qh);

    float rs0 = 0.f, rs1 = 0.f;
    int slot = 0;

    for (int t = 0; t < nt; t++) {
        if (t + 1 < nt) CP_WAIT1(); else CP_WAIT0();
        __syncthreads();                        // tile t visible; compute(t-1) done
        if (t + 2 < nt) {
            int s2 = slot + 2; if (s2 >= 3) s2 -= 3;
            CP_ASYNC16(ks_sh + s2*KT_B + kdst, ksrc + (size_t)(col0 + (t+2)*64) * CQD);
            CP_COMMIT();
        }
        const float* ksb = ks3 + slot*KT_F;

#pragma unroll
        for (int pair = 0; pair < 2; pair++) {
            int j0 = (wc << 5) + (pair << 4);
            float e0[4] = {0.f, 0.f, 0.f, 0.f};
            float e1[4] = {0.f, 0.f, 0.f, 0.f};
#pragma unroll
            for (int s = 0; s < 2; s++) {
                float fa0 = ksb[(j0 + lr    ) * 20 + s*8 + lk    ];
                float fa1 = ksb[(j0 + lr    ) * 20 + s*8 + lk + 4];
                float fb0 = ksb[(j0 + 8 + lr) * 20 + s*8 + lk    ];
                float fb1 = ksb[(j0 + 8 + lr) * 20 + s*8 + lk + 4];
                unsigned ah0 = f2tf(fa0), ah1 = f2tf(fa1);
                unsigned al0 = f2tf(fa0 - __uint_as_float(ah0));
                unsigned al1 = f2tf(fa1 - __uint_as_float(ah1));
                unsigned bh0 = f2tf(fb0), bh1 = f2tf(fb1);
                unsigned bl0 = f2tf(fb0 - __uint_as_float(bh0));
                unsigned bl1 = f2tf(fb1 - __uint_as_float(bh1));
                mma_tf32(e0, qh[s][0], qh[s][1], qh[s][2], qh[s][3], ah0, ah1);
                mma_tf32(e1, qh[s][0], qh[s][1], qh[s][2], qh[s][3], bh0, bh1);
                mma_tf32(e0, qh[s][0], qh[s][1], qh[s][2], qh[s][3], al0, al1);
                mma_tf32(e1, qh[s][0], qh[s][1], qh[s][2], qh[s][3], bl0, bl1);
            }
            rs0 += ex2f(e0[0]) + ex2f(e0[1]) + ex2f(e1[0]) + ex2f(e1[1]);
            rs1 += ex2f(e0[2]) + ex2f(e0[3]) + ex2f(e1[2]) + ex2f(e1[3]);
        }
        if (++slot == 3) slot = 0;
    }

    rs0 += __shfl_xor_sync(0xffffffffu, rs0, 1);
    rs0 += __shfl_xor_sync(0xffffffffu, rs0, 2);
    rs1 += __shfl_xor_sync(0xffffffffu, rs1, 1);
    rs1 += __shfl_xor_sync(0xffffffffu, rs1, 2);
    if (lk == 0) {
        red[iw + lr    ][wc] = rs0;
        red[iw + lr + 8][wc] = rs1;
    }
    __syncthreads();
    if (tid < 64)
        g_Spart[(((size_t)b*4 + g) << 12) + i0 + tid] = red[tid][0] + red[tid][1];
}

// ======================= K5: main pass =======================================
// FA2-style: p stays in registers as the PV A operand. e-phase runs ILP-2
// accumulator pairs; exp is raw ex2 (q pre-scaled by log2e).
#define VT_B (128*72*2)
#define ATTN_SMEM (5120 + 3*KT_B + 3*VT_B + 256)

__global__ void __launch_bounds__(256, 2) attn_main(float* __restrict__ out)
{
    extern __shared__ char smem_raw[];
    float*          qsm  = (float*)smem_raw;
    float*          ks3  = qsm + 64*20;
    __nv_bfloat16*  vsm  = (__nv_bfloat16*)(ks3 + 3*KT_F);
    float*          sinv = (float*)(vsm + 3*128*72);

    int b = blockIdx.x & 3;
    int item = blockIdx.x >> 2;
    int r, g; decode_item(item, r, g);

    int tid = threadIdx.x;
    int i0 = r << 6;
    int col0 = g << 10;
    int colEnd = min((r + 1) << 6, col0 + 1024);
    int nt = (colEnd - col0) >> 6;
    int ngg = (r >> 4) + 1;

    float* attnb = out + OUT_OFF + ((size_t)b << 24);
    const __nv_bfloat16* vbat = g_v + (size_t)b*CDIM*NPOS;

    unsigned ks_sh = (unsigned)__cvta_generic_to_shared(ks3);
    unsigned vs_sh = (unsigned)__cvta_generic_to_shared(vsm);
    unsigned kdst  = (tid >> 2) * 80 + (tid & 3) * 16;
    const float* ksrc = g_k + ((size_t)(b << 12) + (tid >> 2)) * CQD + (tid & 3) * 4;

    auto stage_tile = [&](int jc, int slot) {
        CP_ASYNC16(ks_sh + slot*KT_B + kdst, ksrc + (size_t)jc * CQD);
#pragma unroll
        for (int it = 0; it < 4; it++) {
            int idx = it * 256 + tid;
            int c = idx >> 3, ch = idx & 7;
            CP_ASYNC16(vs_sh + slot*VT_B + c*144 + ch*16,
                       vbat + (size_t)c*NPOS + jc + ch*8);
        }
        CP_COMMIT();
    };

    if (tid < 64) {
        float s = 0.f;
        for (int gg = 0; gg < ngg; gg++)
            s += g_Spart[(((size_t)b*4 + gg) << 12) + i0 + tid];
        sinv[tid] = 1.0f / s;
    }
    // stage q tile
    {
        const float4 qv = ((const float4*)(g_q +
            ((size_t)(b << 12) + i0 + (tid >> 2)) * CQD))[tid & 3];
        *(float4*)&qsm[(tid >> 2) * 20 + (tid & 3) * 4] = qv;
    }
    // prologue: tiles 0 (+1)
    stage_tile(col0, 0);
    if (nt > 1) stage_tile(col0 + 64, 1);
    __syncthreads();

    int w = tid >> 5, lane = tid & 31;
    int wr = w & 3, wc = w >> 2;
    int iw = wr << 4;                 // warp i-base (both phases)
    int lr = lane >> 2, lk = lane & 3;

    float inv0 = sinv[iw + lr], inv1 = sinv[iw + lr + 8];

    unsigned qh[2][4], ql[2][4];
    load_q_frags(qsm, iw, lr, lk, qh, ql);

    // PV B-frag (V^T) ldmatrix base: rows = c, cols = j within slot
    unsigned bV0 = vs_sh + ((lane & 7) + ((lane >> 4) << 3)) * 144
                 + ((wc << 5) + (((lane >> 3) & 1) << 3)) * 2;

    float acc[16][4];
#pragma unroll
    for (int a = 0; a < 16; a++)
#pragma unroll
        for (int c = 0; c < 4; c++) acc[a][c] = 0.f;

    int slot = 0;
    for (int t = 0; t < nt; t++) {
        int jcol0 = col0 + t * 64;
        if (t + 1 < nt) CP_WAIT1(); else CP_WAIT0();
        __syncthreads();   // tile t visible; all warps past PV(t-1)
        if (t + 2 < nt) {
            int s2 = slot + 2; if (s2 >= 3) s2 -= 3;
            stage_tile(jcol0 + 128, s2);
        }

        const float* ksb = ks3 + slot*KT_F;
        unsigned pa[2][4];   // PV A-frags: [k-block][a0..a3]

        // ---- e via 3 tf32 MMAs, ILP-2 pairs; write attn, keep p in regs ----
        float* arow0 = attnb + (size_t)(i0 + iw + lr) * NPOS + jcol0;
        float* arow1 = arow0 + (size_t)8 * NPOS;
#pragma unroll
        for (int pair = 0; pair < 2; pair++) {
            int j0 = (wc << 5) + (pair << 4);
            float e0[4] = {0.f, 0.f, 0.f, 0.f};
            float e1[4] = {0.f, 0.f, 0.f, 0.f};
#pragma unroll
            for (int s = 0; s < 2; s++) {
                float fa0 = ksb[(j0 + lr    ) * 20 + s*8 + lk    ];
                float fa1 = ksb[(j0 + lr    ) * 20 + s*8 + lk + 4];
                float fb0 = ksb[(j0 + 8 + lr) * 20 + s*8 + lk    ];
                float fb1 = ksb[(j0 + 8 + lr) * 20 + s*8 + lk + 4];
                unsigned ah0 = f2tf(fa0), ah1 = f2tf(fa1);
                unsigned al0 = f2tf(fa0 - __uint_as_float(ah0));
                unsigned al1 = f2tf(fa1 - __uint_as_float(ah1));
                unsigned bh0 = f2tf(fb0), bh1 = f2tf(fb1);
                unsigned bl0 = f2tf(fb0 - __uint_as_float(bh0));
                unsigned bl1 = f2tf(fb1 - __uint_as_float(bh1));
                mma_tf32(e0, qh[s][0], qh[s][1], qh[s][2], qh[s][3], ah0, ah1);
                mma_tf32(e1, qh[s][0], qh[s][1], qh[s][2], qh[s][3], bh0, bh1);
                mma_tf32(e0, qh[s][0], qh[s][1], qh[s][2], qh[s][3], al0, al1);
                mma_tf32(e1, qh[s][0], qh[s][1], qh[s][2], qh[s][3], bl0, bl1);
                mma_tf32(e0, ql[s][0], ql[s][1], ql[s][2], ql[s][3], ah0, ah1);
                mma_tf32(e1, ql[s][0], ql[s][1], ql[s][2], ql[s][3], bh0, bh1);
            }
            float p00 = ex2f(e0[0]) * inv0;
            float p01 = ex2f(e0[1]) * inv0;
            float p02 = ex2f(e0[2]) * inv1;
            float p03 = ex2f(e0[3]) * inv1;
            float p10 = ex2f(e1[0]) * inv0;
            float p11 = ex2f(e1[1]) * inv0;
            float p12 = ex2f(e1[2]) * inv1;
            float p13 = ex2f(e1[3]) * inv1;
            int jloc0 = j0 + (lk << 1);
            *(float2*)(arow0 + jloc0)     = make_float2(p00, p01);
            *(float2*)(arow1 + jloc0)     = make_float2(p02, p03);
            *(float2*)(arow0 + jloc0 + 8) = make_float2(p10, p11);
            *(float2*)(arow1 + jloc0 + 8) = make_float2(p12, p13);
            // bf16 A-frag layout: a0=(row lr,k0-7) a1=(row lr+8,k0-7)
            //                     a2=(row lr,k8-15) a3=(row lr+8,k8-15)
            pa[pair][0] = pack_bf16x2(p00, p01);   // row lr,   k 0-7
            pa[pair][1] = pack_bf16x2(p02, p03);   // row lr+8, k 0-7
            pa[pair][2] = pack_bf16x2(p10, p11);   // row lr,   k 8-15
            pa[pair][3] = pack_bf16x2(p12, p13);   // row lr+8, k 8-15
        }

        // ---- PV: out[i][c] += p[i][j] * V^T[j][c]; A from regs, B via ldsm --
        unsigned bbase = bV0 + slot*VT_B;
#pragma unroll
        for (int kb = 0; kb < 2; kb++) {
#pragma unroll
            for (int cg = 0; cg < 8; cg++) {
                unsigned b0, b1, b2, b3;
                ldsm_x4(b0, b1, b2, b3, bbase + cg*2304 + kb*32);
                mma_bf16(acc[cg*2    ], pa[kb][0], pa[kb][1], pa[kb][2], pa[kb][3], b0, b1);
                mma_bf16(acc[cg*2 + 1], pa[kb][0], pa[kb][1], pa[kb][2], pa[kb][3], b2, b3);
            }
        }
        if (++slot == 3) slot = 0;
    }

    // ---- cross-warp reduce (wc=1 -> wc=0) and store partial PV -------------
    __syncthreads();                    // all PV reads of vsm done
    float* redbuf = (float*)vsm;        // 32KB scratch inside freed vsm
    if (wc == 1) {
        float* dst = redbuf + wr*2048 + lane;
#pragma unroll
        for (int a = 0; a < 16; a++)
#pragma unroll
            for (int c = 0; c < 4; c++)
                dst[(a*4 + c) * 32] = acc[a][c];
    }
    __syncthreads();
    if (wc == 0) {
        const float* src = redbuf + wr*2048 + lane;
        float* vp = g_Vpart + (((size_t)b*4 + g) * CDIM) * NPOS;
        int gi = lane >> 2, t2 = (lane & 3) << 1;
        int ii = i0 + iw + gi;
#pragma unroll
        for (int a = 0; a < 16; a++) {
            float v0 = acc[a][0] + src[(a*4 + 0) * 32];
            float v1 = acc[a][1] + src[(a*4 + 1) * 32];
            float v2 = acc[a][2] + src[(a*4 + 2) * 32];
            float v3 = acc[a][3] + src[(a*4 + 3) * 32];
            int cc = a*8 + t2;
            vp[(size_t)cc*NPOS + ii]         = v0;
            vp[(size_t)(cc+1)*NPOS + ii]     = v1;
            vp[(size_t)cc*NPOS + ii + 8]     = v2;
            vp[(size_t)(cc+1)*NPOS + ii + 8] = v3;
        }
    }

    // ---- fused mask-zero epilogue: rows n ≡ item (mod 160) of this batch ----
    {
        float4 z = make_float4(0.f, 0.f, 0.f, 0.f);
        for (int n = item; n < NPOS; n += 160) {
            int L = ((n >> 6) + 1) << 6;
            if (L >= NPOS) continue;
            float4* dst = (float4*)(attnb + (size_t)n * NPOS + L);
            int cnt4 = (NPOS - L) >> 2;
            for (int t4 = tid; t4 < cnt4; t4 += 256) dst[t4] = z;
        }
    }
}

// ======================= K7: finalize ========================================
__global__ void __launch_bounds__(256) finalize(
    const float* __restrict__ x, const float* __restrict__ gamma,
    float* __restrict__ out)
{
    int t = blockIdx.x * 256 + threadIdx.x;    // < B*C*N
    int n  = t & (NPOS - 1);
    int bc = t >> 12;
    int b  = bc >> 7;
    int c  = bc & 127;
    int ngg = (n >> 10) + 1;

    const float* vp = g_Vpart + ((size_t)(b*4) * CDIM + c) * NPOS + n;
    float s = 0.f;
    for (int gg = 0; gg < ngg; gg++)
        s += vp[(size_t)gg * CDIM * NPOS];
    out[t] = gamma[0] * s + x[t];
}

// ======================= launch ==============================================
extern "C" void kernel_launch(void* const* d_in, const int* in_sizes, int n_in,
                              void* d_out, int out_size)
{
    const float* x     = (const float*)d_in[0];
    const float* wq    = (const float*)d_in[1];
    const float* bq    = (const float*)d_in[2];
    const float* wk    = (const float*)d_in[3];
    const float* bk    = (const float*)d_in[4];
    const float* wv    = (const float*)d_in[5];
    const float* bv    = (const float*)d_in[6];
    const float* gamma = (const float*)d_in[7];
    float* out = (float*)d_out;

    cudaFuncSetAttribute(attn_main,
                         cudaFuncAttributeMaxDynamicSharedMemorySize, ATTN_SMEM);
    cudaFuncSetAttribute(v_proj,
                         cudaFuncAttributeMaxDynamicSharedMemorySize, VPROJ_SMEM);
    cudaFuncSetAttribute(qk_proj_mma,
                         cudaFuncAttributeMaxDynamicSharedMemorySize, QK_SMEM);

    qk_proj_mma<<<BSZ*64, 256, QK_SMEM>>>(x, wq, bq, wk, bk);
    v_proj<<<BSZ*(NPOS/64), 256, VPROJ_SMEM>>>(x, wv, bv);
    rowsum_k<<<BSZ*160, 256>>>();
    attn_main<<<BSZ*160, 256, ATTN_SMEM>>>(out);
    finalize<<<(BSZ*CDIM*NPOS)/256, 256>>>(x, gamma, out);
}